// round 2
// baseline (speedup 1.0000x reference)
#include <cuda_runtime.h>
#include <cstdint>

#define BATCH 64
#define SEQ   512
#define EMB   128
#define HID   256
#define G4    1024            // 4*HID
#define NTAGS 50
#define M_ROWS (BATCH*SEQ)    // 32768
#define REC_BLOCKS 128        // 2 dirs * 64 hidden-slices
#define NBAR 8                // distributed barrier counters

// ---------------- scratch (device globals; allocation-free) ----------------
__device__ float g_x   [(size_t)M_ROWS*EMB];      // embedded input  [B*T, E]
__device__ float g_xg_f[(size_t)M_ROWS*G4];       // fwd gate pre-acts
__device__ float g_xg_b[(size_t)M_ROWS*G4];       // bwd gate pre-acts
__device__ float g_o1  [(size_t)M_ROWS*2*HID];    // layer1 output [B*T, 2H]
__device__ float g_o2  [(size_t)M_ROWS*2*HID];    // layer2 output
__device__ float g_h   [2][2][HID][BATCH];        // h double buffer [parity][dir][h][b]
__device__ int   g_bar [SEQ][NBAR];               // distributed per-step arrival counters

// ---------------- helpers ----------------
__device__ __forceinline__ int ld_acquire(const int* p) {
    int v;
    asm volatile("ld.global.acquire.gpu.b32 %0, [%1];" : "=r"(v) : "l"(p));
    return v;
}
__device__ __forceinline__ float sigf(float x)  { return 1.f/(1.f + __expf(-x)); }
__device__ __forceinline__ float tanhf_(float x){ return 1.f - 2.f/(__expf(2.f*x) + 1.f); }

// ---------------- embedding gather ----------------
__global__ void embed_kernel(const int* __restrict__ words, const float* __restrict__ emb) {
    int row = blockIdx.x;                 // b*T + t
    int w   = words[row];
    const float4* src = (const float4*)(emb + (size_t)w * EMB);
    float4*       dst = (float4*)(g_x + (size_t)row * EMB);
    dst[threadIdx.x] = src[threadIdx.x];  // 32 threads * 16B = 128 floats
}

// ---------------- per-replay state reset ----------------
__global__ void init_kernel() {
    int i = blockIdx.x * blockDim.x + threadIdx.x;
    float* h = &g_h[0][0][0][0];
    if (i < 2*2*HID*BATCH) h[i] = 0.f;
    if (i < SEQ*NBAR)      (&g_bar[0][0])[i] = 0;
}

// ---------------- generic SGEMM:  C[M,N] = A[M,K] * B[N,K]^T + bias1 + bias2 ----------------
// A row-major [M,K]; Bw row-major [N,K] (weights); C row-major [M,N].
// Requires M % 128 == 0, K % 8 == 0. N arbitrary (guarded).
__global__ __launch_bounds__(256) void sgemm_bias_kernel(
    const float* __restrict__ A, const float* __restrict__ Bw,
    const float* __restrict__ bias1, const float* __restrict__ bias2,
    float* __restrict__ C, int M, int N, int K)
{
    const int BM = 128, BN = 128, BK = 8;
    __shared__ float As[BK][BM];
    __shared__ float Bs[BK][BN];

    int tid = threadIdx.x;
    int m0 = blockIdx.y * BM;
    int n0 = blockIdx.x * BN;
    int ty = tid >> 4;          // 0..15 -> row group
    int tx = tid & 15;          // 0..15 -> col group

    float acc[8][8];
    #pragma unroll
    for (int i = 0; i < 8; i++)
        #pragma unroll
        for (int j = 0; j < 8; j++) acc[i][j] = 0.f;

    int aRow = tid >> 1;            // 0..127
    int aK   = (tid & 1) * 4;       // 0 or 4
    int brow_g = n0 + aRow;
    const float* Aptr = A + (size_t)(m0 + aRow) * K + aK;
    const float* Bptr = Bw + (size_t)brow_g * K + aK;

    for (int k0 = 0; k0 < K; k0 += BK) {
        float4 av = *(const float4*)(Aptr + k0);
        As[aK+0][aRow] = av.x; As[aK+1][aRow] = av.y;
        As[aK+2][aRow] = av.z; As[aK+3][aRow] = av.w;

        float4 bv = make_float4(0.f, 0.f, 0.f, 0.f);
        if (brow_g < N) bv = *(const float4*)(Bptr + k0);
        Bs[aK+0][aRow] = bv.x; Bs[aK+1][aRow] = bv.y;
        Bs[aK+2][aRow] = bv.z; Bs[aK+3][aRow] = bv.w;
        __syncthreads();

        #pragma unroll
        for (int k = 0; k < BK; k++) {
            float4 a0 = *(const float4*)&As[k][ty*8];
            float4 a1 = *(const float4*)&As[k][ty*8+4];
            float4 b0 = *(const float4*)&Bs[k][tx*8];
            float4 b1 = *(const float4*)&Bs[k][tx*8+4];
            float ar[8] = {a0.x,a0.y,a0.z,a0.w,a1.x,a1.y,a1.z,a1.w};
            float br[8] = {b0.x,b0.y,b0.z,b0.w,b1.x,b1.y,b1.z,b1.w};
            #pragma unroll
            for (int i = 0; i < 8; i++)
                #pragma unroll
                for (int j = 0; j < 8; j++)
                    acc[i][j] = fmaf(ar[i], br[j], acc[i][j]);
        }
        __syncthreads();
    }

    #pragma unroll
    for (int i = 0; i < 8; i++) {
        int m = m0 + ty*8 + i;
        #pragma unroll
        for (int j = 0; j < 8; j++) {
            int n = n0 + tx*8 + j;
            if (n < N) {
                float v = acc[i][j] + bias1[n] + (bias2 ? bias2[n] : 0.f);
                C[(size_t)m * N + n] = v;
            }
        }
    }
}

// ---------------- persistent BiLSTM recurrence (one layer, both directions) ----------------
// Grid: 128 blocks. dir = blk>>6, hidden slice j0 = (blk&63)*4 (4 hidden units / block).
// SMEM: Whh slice [256 k][16 rows] (resident all steps), h tile [256][64], gate buf [16][64], lens.
#define SMEM_RECUR ((4096 + 16384 + 1024) * 4 + 64 * 4)

__global__ __launch_bounds__(256, 1) void recur_kernel(
    const float* __restrict__ xg_f, const float* __restrict__ xg_b,
    const float* __restrict__ Whh_f, const float* __restrict__ Whh_b,
    const int* __restrict__ lengths, float* __restrict__ out)
{
    extern __shared__ float smem[];
    float* w_sm    = smem;                 // [256][16]  (k-major, col = g*4+jj)
    float* h_sm    = smem + 4096;          // [256][64]  (k-major over hidden, b minor)
    float* gate_sm = h_sm + 16384;         // [16][64]   ((g*4+jj), b)
    int*   lens_sm = (int*)(gate_sm + 1024);

    const int tid = threadIdx.x;
    const int dir = blockIdx.x >> 6;
    const int j0  = (blockIdx.x & 63) * 4;
    const int myq = blockIdx.x & (NBAR - 1);
    const float* Whh = dir ? Whh_b : Whh_f;
    const float* xg  = dir ? xg_b  : xg_f;

    // Load Whh slice: rows {g*H + j0 + jj : g in 0..3, jj in 0..3}, transposed to k-major.
    for (int idx = tid; idx < 4096; idx += 256) {
        int row = idx >> 8;       // 0..15  == g*4 + jj
        int k   = idx & 255;
        int gg  = row >> 2, jj = row & 3;
        w_sm[k*16 + row] = Whh[(size_t)(gg*HID + j0 + jj) * HID + k];
    }
    if (tid < BATCH) lens_sm[tid] = lengths[tid];

    const int b  = tid & 63;      // compute-phase batch
    const int g  = tid >> 6;      // compute-phase gate (warp-uniform)
    const int cb = tid & 63;      // combine-phase batch
    const int cj = tid >> 6;      // combine-phase jj
    float c_reg = 0.f;
    const float4* w4 = (const float4*)w_sm;

    __syncthreads();

    for (int s = 0; s < SEQ; s++) {
        const int t = dir ? (SEQ - 1 - s) : s;

        if (s > 0) {
            if (tid == 0) {
                int sum;
                do {
                    sum = 0;
                    #pragma unroll
                    for (int q = 0; q < NBAR; q++) sum += ld_acquire(&g_bar[s-1][q]);
                    if (sum < REC_BLOCKS) __nanosleep(64);
                } while (sum < REC_BLOCKS);
            }
            __syncthreads();
        }

        // stage h_prev (all 256 hidden x 64 batch) from L2 (bypass L1: buffer is recycled)
        {
            const float4* hsrc = (const float4*)&g_h[s & 1][dir][0][0];
            float4* hdst = (float4*)h_sm;
            for (int i = tid; i < 4096; i += 256) hdst[i] = __ldcg(&hsrc[i]);
        }
        __syncthreads();

        // gates: acc[jj] = xg[b,t,g*H+j0+jj] + sum_k Whh[g*H+j0+jj, k] * h_prev[b, k]
        float4 a = __ldg((const float4*)(xg + ((size_t)b * SEQ + t) * G4 + g * HID + j0));
        float a0 = a.x, a1 = a.y, a2 = a.z, a3 = a.w;
        #pragma unroll 8
        for (int k = 0; k < HID; k++) {
            float  hv = h_sm[k*64 + b];
            float4 w  = w4[k*4 + g];
            a0 = fmaf(w.x, hv, a0);
            a1 = fmaf(w.y, hv, a1);
            a2 = fmaf(w.z, hv, a2);
            a3 = fmaf(w.w, hv, a3);
        }
        gate_sm[(g*4 + 0)*64 + b] = a0;
        gate_sm[(g*4 + 1)*64 + b] = a1;
        gate_sm[(g*4 + 2)*64 + b] = a2;
        gate_sm[(g*4 + 3)*64 + b] = a3;
        __syncthreads();

        // combine: i,f,g,o -> c,h with masking
        {
            float ig = gate_sm[(0*4 + cj)*64 + cb];
            float fg = gate_sm[(1*4 + cj)*64 + cb];
            float gg = gate_sm[(2*4 + cj)*64 + cb];
            float og = gate_sm[(3*4 + cj)*64 + cb];
            float c_new = sigf(fg) * c_reg + sigf(ig) * tanhf_(gg);
            float h_new = sigf(og) * tanhf_(c_new);
            float h_prev = h_sm[(j0 + cj)*64 + cb];
            bool  m = (t < lens_sm[cb]);
            float h_out = m ? h_new : h_prev;
            c_reg       = m ? c_new : c_reg;

            g_h[(s + 1) & 1][dir][j0 + cj][cb] = h_out;
            out[((size_t)cb * SEQ + t) * (2*HID) + dir*HID + j0 + cj] = h_out;
        }
        __threadfence();
        __syncthreads();
        if (tid == 0) atomicAdd(&g_bar[s][myq], 1);
    }
}

// ---------------- launch ----------------
extern "C" void kernel_launch(void* const* d_in, const int* in_sizes, int n_in,
                              void* d_out, int out_size)
{
    (void)in_sizes; (void)n_in; (void)out_size;
    const int*   words    = (const int*)  d_in[0];
    const int*   lengths  = (const int*)  d_in[1];
    const float* emb      = (const float*)d_in[2];
    const float* l1f_Wih  = (const float*)d_in[3];
    const float* l1f_Whh  = (const float*)d_in[4];
    const float* l1f_bih  = (const float*)d_in[5];
    const float* l1f_bhh  = (const float*)d_in[6];
    const float* l1b_Wih  = (const float*)d_in[7];
    const float* l1b_Whh  = (const float*)d_in[8];
    const float* l1b_bih  = (const float*)d_in[9];
    const float* l1b_bhh  = (const float*)d_in[10];
    const float* l2f_Wih  = (const float*)d_in[11];
    const float* l2f_Whh  = (const float*)d_in[12];
    const float* l2f_bih  = (const float*)d_in[13];
    const float* l2f_bhh  = (const float*)d_in[14];
    const float* l2b_Wih  = (const float*)d_in[15];
    const float* l2b_Whh  = (const float*)d_in[16];
    const float* l2b_bih  = (const float*)d_in[17];
    const float* l2b_bhh  = (const float*)d_in[18];
    const float* cls_W    = (const float*)d_in[19];
    const float* cls_b    = (const float*)d_in[20];
    float* out = (float*)d_out;

    float *px, *pxf, *pxb, *po1, *po2;
    cudaGetSymbolAddress((void**)&px,  g_x);
    cudaGetSymbolAddress((void**)&pxf, g_xg_f);
    cudaGetSymbolAddress((void**)&pxb, g_xg_b);
    cudaGetSymbolAddress((void**)&po1, g_o1);
    cudaGetSymbolAddress((void**)&po2, g_o2);

    cudaFuncSetAttribute(recur_kernel, cudaFuncAttributeMaxDynamicSharedMemorySize, SMEM_RECUR);

    // 1) embedding
    embed_kernel<<<M_ROWS, 32>>>(words, emb);

    // 2) layer-1 input projections (bias = bih + bhh folded in)
    dim3 gx(G4/128, M_ROWS/128);
    sgemm_bias_kernel<<<gx, 256>>>(px, l1f_Wih, l1f_bih, l1f_bhh, pxf, M_ROWS, G4, EMB);
    sgemm_bias_kernel<<<gx, 256>>>(px, l1b_Wih, l1b_bih, l1b_bhh, pxb, M_ROWS, G4, EMB);

    // 3) layer-1 recurrence
    init_kernel<<<256, 256>>>();
    recur_kernel<<<REC_BLOCKS, 256, SMEM_RECUR>>>(pxf, pxb, l1f_Whh, l1b_Whh, lengths, po1);

    // 4) layer-2 input projections
    sgemm_bias_kernel<<<gx, 256>>>(po1, l2f_Wih, l2f_bih, l2f_bhh, pxf, M_ROWS, G4, 2*HID);
    sgemm_bias_kernel<<<gx, 256>>>(po1, l2b_Wih, l2b_bih, l2b_bhh, pxb, M_ROWS, G4, 2*HID);

    // 5) layer-2 recurrence
    init_kernel<<<256, 256>>>();
    recur_kernel<<<REC_BLOCKS, 256, SMEM_RECUR>>>(pxf, pxb, l2f_Whh, l2b_Whh, lengths, po2);

    // 6) classifier
    dim3 gc((NTAGS + 127)/128, M_ROWS/128);
    sgemm_bias_kernel<<<gc, 256>>>(po2, cls_W, cls_b, nullptr, out, M_ROWS, NTAGS, 2*HID);
}

// round 4
// speedup vs baseline: 1.0806x; 1.0806x over previous
#include <cuda_runtime.h>
#include <cstdint>

#define BATCH 64
#define SEQ   512
#define EMB   128
#define HID   256
#define G4    1024            // 4*HID
#define NTAGS 50
#define M_ROWS (BATCH*SEQ)    // 32768
#define REC_BLOCKS 128        // 2 dirs * 32 j-slices * 2 batch-halves
#define NBAR 8                // distributed barrier counters

// ---------------- scratch (device globals; allocation-free) ----------------
__device__ float g_x   [(size_t)M_ROWS*EMB];      // embedded input  [B*T, E]
__device__ float g_xg_f[(size_t)M_ROWS*G4];       // fwd gate pre-acts
__device__ float g_xg_b[(size_t)M_ROWS*G4];       // bwd gate pre-acts
__device__ float g_o1  [(size_t)M_ROWS*2*HID];    // layer1 output [B*T, 2H]
__device__ float g_o2  [(size_t)M_ROWS*2*HID];    // layer2 output
__device__ float g_h   [2][2][HID][BATCH];        // h double buffer [parity][dir][h][b]
__device__ int   g_bar [SEQ][NBAR];               // distributed per-step arrival counters

// ---------------- helpers ----------------
__device__ __forceinline__ int ld_acquire(const int* p) {
    int v;
    asm volatile("ld.global.acquire.gpu.b32 %0, [%1];" : "=r"(v) : "l"(p));
    return v;
}
__device__ __forceinline__ void red_release_add(int* p, int v) {
    asm volatile("red.release.gpu.global.add.u32 [%0], %1;" :: "l"(p), "r"(v) : "memory");
}
__device__ __forceinline__ float sigf(float x)  { return 1.f/(1.f + __expf(-x)); }
__device__ __forceinline__ float tanhf_(float x){ return 1.f - 2.f/(__expf(2.f*x) + 1.f); }

// ---------------- embedding gather ----------------
__global__ void embed_kernel(const int* __restrict__ words, const float* __restrict__ emb) {
    int row = blockIdx.x;                 // b*T + t
    int w   = words[row];
    const float4* src = (const float4*)(emb + (size_t)w * EMB);
    float4*       dst = (float4*)(g_x + (size_t)row * EMB);
    dst[threadIdx.x] = src[threadIdx.x];  // 32 threads * 16B = 128 floats
}

// ---------------- per-replay state reset ----------------
__global__ void init_kernel() {
    int i = blockIdx.x * blockDim.x + threadIdx.x;
    float* h = &g_h[0][0][0][0];
    if (i < 2*2*HID*BATCH) h[i] = 0.f;
    if (i < SEQ*NBAR)      (&g_bar[0][0])[i] = 0;
}

// ---------------- double-buffered SGEMM:  C[M,N] = A[M,K]*Bw[N,K]^T + bias1 (+bias2) --------
// A row-major [M,K]; Bw row-major [N,K]; C row-major [M,N].
// Requires M % 128 == 0, K % 16 == 0. N arbitrary (guarded).
__global__ __launch_bounds__(256) void sgemm_db_kernel(
    const float* __restrict__ A, const float* __restrict__ Bw,
    const float* __restrict__ bias1, const float* __restrict__ bias2,
    float* __restrict__ C, int M, int N, int K)
{
    const int BM = 128, BN = 128, BK = 16;
    __shared__ float As[2][BK][BM];
    __shared__ float Bs[2][BK][BN];

    const int tid = threadIdx.x;
    const int m0 = blockIdx.y * BM;
    const int n0 = blockIdx.x * BN;
    const int ty = tid >> 4;          // 0..15
    const int tx = tid & 15;          // 0..15

    // loader mapping: each thread loads 2 float4 from A and 2 from B per tile
    const int lr = tid >> 2;          // 0..63
    const int lk = (tid & 3) * 4;     // 0,4,8,12
    const float* Aptr0 = A + (size_t)(m0 + lr)      * K + lk;
    const float* Aptr1 = A + (size_t)(m0 + 64 + lr) * K + lk;
    const int bn0 = n0 + lr, bn1 = n0 + 64 + lr;
    const float* Bptr0 = Bw + (size_t)bn0 * K + lk;
    const float* Bptr1 = Bw + (size_t)bn1 * K + lk;
    const bool b0ok = bn0 < N, b1ok = bn1 < N;

    float acc[8][8];
    #pragma unroll
    for (int i = 0; i < 8; i++)
        #pragma unroll
        for (int j = 0; j < 8; j++) acc[i][j] = 0.f;

    const float4 z4 = make_float4(0.f,0.f,0.f,0.f);
    float4 av0, av1, bv0, bv1;

    // prologue: tile 0 -> buf 0
    av0 = *(const float4*)Aptr0;
    av1 = *(const float4*)Aptr1;
    bv0 = b0ok ? *(const float4*)Bptr0 : z4;
    bv1 = b1ok ? *(const float4*)Bptr1 : z4;
    As[0][lk+0][lr] = av0.x; As[0][lk+1][lr] = av0.y; As[0][lk+2][lr] = av0.z; As[0][lk+3][lr] = av0.w;
    As[0][lk+0][64+lr] = av1.x; As[0][lk+1][64+lr] = av1.y; As[0][lk+2][64+lr] = av1.z; As[0][lk+3][64+lr] = av1.w;
    Bs[0][lk+0][lr] = bv0.x; Bs[0][lk+1][lr] = bv0.y; Bs[0][lk+2][lr] = bv0.z; Bs[0][lk+3][lr] = bv0.w;
    Bs[0][lk+0][64+lr] = bv1.x; Bs[0][lk+1][64+lr] = bv1.y; Bs[0][lk+2][64+lr] = bv1.z; Bs[0][lk+3][64+lr] = bv1.w;
    __syncthreads();

    const int T = K / BK;
    for (int tI = 0; tI < T; tI++) {
        const int buf = tI & 1;
        const bool more = (tI + 1 < T);
        if (more) {
            const int off = (tI + 1) * BK;
            av0 = *(const float4*)(Aptr0 + off);
            av1 = *(const float4*)(Aptr1 + off);
            bv0 = b0ok ? *(const float4*)(Bptr0 + off) : z4;
            bv1 = b1ok ? *(const float4*)(Bptr1 + off) : z4;
        }
        #pragma unroll
        for (int k = 0; k < BK; k++) {
            float4 a0 = *(const float4*)&As[buf][k][ty*8];
            float4 a1 = *(const float4*)&As[buf][k][ty*8+4];
            float4 b0 = *(const float4*)&Bs[buf][k][tx*8];
            float4 b1 = *(const float4*)&Bs[buf][k][tx*8+4];
            float ar[8] = {a0.x,a0.y,a0.z,a0.w,a1.x,a1.y,a1.z,a1.w};
            float br[8] = {b0.x,b0.y,b0.z,b0.w,b1.x,b1.y,b1.z,b1.w};
            #pragma unroll
            for (int i = 0; i < 8; i++)
                #pragma unroll
                for (int j = 0; j < 8; j++)
                    acc[i][j] = fmaf(ar[i], br[j], acc[i][j]);
        }
        if (more) {
            const int nb = buf ^ 1;
            __syncthreads();
            As[nb][lk+0][lr] = av0.x; As[nb][lk+1][lr] = av0.y; As[nb][lk+2][lr] = av0.z; As[nb][lk+3][lr] = av0.w;
            As[nb][lk+0][64+lr] = av1.x; As[nb][lk+1][64+lr] = av1.y; As[nb][lk+2][64+lr] = av1.z; As[nb][lk+3][64+lr] = av1.w;
            Bs[nb][lk+0][lr] = bv0.x; Bs[nb][lk+1][lr] = bv0.y; Bs[nb][lk+2][lr] = bv0.z; Bs[nb][lk+3][lr] = bv0.w;
            Bs[nb][lk+0][64+lr] = bv1.x; Bs[nb][lk+1][64+lr] = bv1.y; Bs[nb][lk+2][64+lr] = bv1.z; Bs[nb][lk+3][64+lr] = bv1.w;
            __syncthreads();
        }
    }

    #pragma unroll
    for (int i = 0; i < 8; i++) {
        int m = m0 + ty*8 + i;
        #pragma unroll
        for (int j = 0; j < 8; j++) {
            int n = n0 + tx*8 + j;
            if (n < N) {
                float v = acc[i][j] + bias1[n] + (bias2 ? bias2[n] : 0.f);
                C[(size_t)m * N + n] = v;
            }
        }
    }
}

// ---------------- persistent BiLSTM recurrence (one layer, both directions) ----------------
// 128 blocks = dir(2) x jslice(32) x bhalf(2). Block: 32 gate-rows (8 j x 4 gates) x 32 batch.
// SMEM: w [256][32] resident, h [256][32] staged per step, gate [32][32], hst [8][32], lens[32].
#define SMEM_RECUR ((8192 + 8192 + 1024 + 256) * 4 + 32 * 4)

__global__ __launch_bounds__(256, 1) void recur_kernel(
    const float* __restrict__ xg_f, const float* __restrict__ xg_b,
    const float* __restrict__ Whh_f, const float* __restrict__ Whh_b,
    const int* __restrict__ lengths, float* __restrict__ out)
{
    extern __shared__ float smem[];
    float* w_sm    = smem;                 // [256 k][32 r]   r = g*8+jj
    float* h_sm    = smem + 8192;          // [256 k][32 b]
    float* gate_sm = h_sm + 8192;          // [32 r][32 b]
    float* hst     = gate_sm + 1024;       // [8 jj][32 b]
    int*   lens_sm = (int*)(hst + 256);    // [32]

    const int tid = threadIdx.x;
    const int blk = blockIdx.x;
    const int dir    = blk >> 6;
    const int jslice = (blk >> 1) & 31;
    const int bh     = blk & 1;
    const int j0 = jslice * 8;
    const int b0 = bh * 32;
    const int myq = blk & (NBAR - 1);
    const float* Whh = dir ? Whh_b : Whh_f;
    const float* xg  = dir ? xg_b  : xg_f;

    // Load Whh slice (one-time): rows r = g*8+jj -> Whh[g*HID + j0 + jj][k], k-major in smem.
    for (int idx = tid; idx < 8192; idx += 256) {
        int r = idx >> 8;         // 0..31
        int k = idx & 255;
        int g = r >> 3, jj = r & 7;
        w_sm[k*32 + r] = Whh[(size_t)(g*HID + j0 + jj) * HID + k];
    }
    if (tid < 32) lens_sm[tid] = lengths[b0 + tid];

    const int lane = tid & 31;
    const int rg   = tid >> 5;            // warp id 0..7; handles rows 4rg..4rg+3
    const int ggate = rg >> 1;
    const int xoff  = ggate*HID + j0 + (rg & 1)*4;
    const int b     = b0 + lane;
    const float4* w4 = (const float4*)w_sm;
    float c_reg = 0.f;

    __syncthreads();

    int t0 = dir ? (SEQ - 1) : 0;
    float4 a_cur = __ldg((const float4*)(xg + ((size_t)b * SEQ + t0) * G4 + xoff));

    for (int s = 0; s < SEQ; s++) {
        const int t = dir ? (SEQ - 1 - s) : s;

        // prefetch next step's xg (independent of barrier; overlaps the spin)
        float4 a_next = make_float4(0.f,0.f,0.f,0.f);
        if (s + 1 < SEQ) {
            int tn = dir ? (SEQ - 2 - s) : (s + 1);
            a_next = __ldg((const float4*)(xg + ((size_t)b * SEQ + tn) * G4 + xoff));
        }

        if (s > 0) {
            if (tid == 0) {
                int sum;
                do {
                    sum = 0;
                    #pragma unroll
                    for (int q = 0; q < NBAR; q++) sum += ld_acquire(&g_bar[s-1][q]);
                    if (sum < REC_BLOCKS) __nanosleep(64);
                } while (sum < REC_BLOCKS);
            }
            __syncthreads();
        }

        // stage h_prev [256 k][our 32 b] from L2 (bypass L1; buffer parity recycles)
        {
            const float* hsrc = &g_h[s & 1][dir][0][0];
            for (int i = tid; i < 2048; i += 256) {   // 2048 float4 = 32KB
                int k = i >> 3, o = i & 7;
                float4 v = __ldcg((const float4*)(hsrc + k*BATCH + b0 + o*4));
                *(float4*)(h_sm + k*32 + o*4) = v;
            }
        }
        __syncthreads();

        // gates: rows 4rg..4rg+3 for batch b
        float acc0 = a_cur.x, acc1 = a_cur.y, acc2 = a_cur.z, acc3 = a_cur.w;
        #pragma unroll 8
        for (int k = 0; k < HID; k++) {
            float  hv = h_sm[k*32 + lane];
            float4 w  = w4[k*8 + rg];       // broadcast within warp
            acc0 = fmaf(w.x, hv, acc0);
            acc1 = fmaf(w.y, hv, acc1);
            acc2 = fmaf(w.z, hv, acc2);
            acc3 = fmaf(w.w, hv, acc3);
        }
        gate_sm[(rg*4+0)*32 + lane] = acc0;
        gate_sm[(rg*4+1)*32 + lane] = acc1;
        gate_sm[(rg*4+2)*32 + lane] = acc2;
        gate_sm[(rg*4+3)*32 + lane] = acc3;
        __syncthreads();

        // combine: thread = (jj=rg, batch=lane)
        {
            const int cjj = rg;
            float ig = gate_sm[(0*8 + cjj)*32 + lane];
            float fg = gate_sm[(1*8 + cjj)*32 + lane];
            float gv = gate_sm[(2*8 + cjj)*32 + lane];
            float og = gate_sm[(3*8 + cjj)*32 + lane];
            float c_new = sigf(fg) * c_reg + sigf(ig) * tanhf_(gv);
            float h_new = sigf(og) * tanhf_(c_new);
            float h_prev = h_sm[(j0 + cjj)*32 + lane];
            bool  m = (t < lens_sm[lane]);
            float h_out = m ? h_new : h_prev;
            c_reg       = m ? c_new : c_reg;
            g_h[(s + 1) & 1][dir][j0 + cjj][b] = h_out;
            hst[cjj*32 + lane] = h_out;
        }
        __syncthreads();
        if (tid == 0) red_release_add(&g_bar[s][myq], 1);

        // semi-coalesced out store: 64 threads x float4 (8 j's per (b,t) as 2x16B)
        if (tid < 64) {
            int bb  = tid >> 1;           // 0..31
            int seg = tid & 1;            // 0..1
            float4 v;
            v.x = hst[(seg*4+0)*32 + bb];
            v.y = hst[(seg*4+1)*32 + bb];
            v.z = hst[(seg*4+2)*32 + bb];
            v.w = hst[(seg*4+3)*32 + bb];
            *(float4*)(out + ((size_t)(b0 + bb) * SEQ + t) * (2*HID) + dir*HID + j0 + seg*4) = v;
        }

        a_cur = a_next;
    }
}

// ---------------- launch ----------------
extern "C" void kernel_launch(void* const* d_in, const int* in_sizes, int n_in,
                              void* d_out, int out_size)
{
    (void)in_sizes; (void)n_in; (void)out_size;
    const int*   words    = (const int*)  d_in[0];
    const int*   lengths  = (const int*)  d_in[1];
    const float* emb      = (const float*)d_in[2];
    const float* l1f_Wih  = (const float*)d_in[3];
    const float* l1f_Whh  = (const float*)d_in[4];
    const float* l1f_bih  = (const float*)d_in[5];
    const float* l1f_bhh  = (const float*)d_in[6];
    const float* l1b_Wih  = (const float*)d_in[7];
    const float* l1b_Whh  = (const float*)d_in[8];
    const float* l1b_bih  = (const float*)d_in[9];
    const float* l1b_bhh  = (const float*)d_in[10];
    const float* l2f_Wih  = (const float*)d_in[11];
    const float* l2f_Whh  = (const float*)d_in[12];
    const float* l2f_bih  = (const float*)d_in[13];
    const float* l2f_bhh  = (const float*)d_in[14];
    const float* l2b_Wih  = (const float*)d_in[15];
    const float* l2b_Whh  = (const float*)d_in[16];
    const float* l2b_bih  = (const float*)d_in[17];
    const float* l2b_bhh  = (const float*)d_in[18];
    const float* cls_W    = (const float*)d_in[19];
    const float* cls_b    = (const float*)d_in[20];
    float* out = (float*)d_out;

    float *px, *pxf, *pxb, *po1, *po2;
    cudaGetSymbolAddress((void**)&px,  g_x);
    cudaGetSymbolAddress((void**)&pxf, g_xg_f);
    cudaGetSymbolAddress((void**)&pxb, g_xg_b);
    cudaGetSymbolAddress((void**)&po1, g_o1);
    cudaGetSymbolAddress((void**)&po2, g_o2);

    cudaFuncSetAttribute(recur_kernel, cudaFuncAttributeMaxDynamicSharedMemorySize, SMEM_RECUR);

    // 1) embedding
    embed_kernel<<<M_ROWS, 32>>>(words, emb);

    // 2) layer-1 input projections (bias = bih + bhh folded in)
    dim3 gx(G4/128, M_ROWS/128);
    sgemm_db_kernel<<<gx, 256>>>(px, l1f_Wih, l1f_bih, l1f_bhh, pxf, M_ROWS, G4, EMB);
    sgemm_db_kernel<<<gx, 256>>>(px, l1b_Wih, l1b_bih, l1b_bhh, pxb, M_ROWS, G4, EMB);

    // 3) layer-1 recurrence
    init_kernel<<<256, 256>>>();
    recur_kernel<<<REC_BLOCKS, 256, SMEM_RECUR>>>(pxf, pxb, l1f_Whh, l1b_Whh, lengths, po1);

    // 4) layer-2 input projections
    sgemm_db_kernel<<<gx, 256>>>(po1, l2f_Wih, l2f_bih, l2f_bhh, pxf, M_ROWS, G4, 2*HID);
    sgemm_db_kernel<<<gx, 256>>>(po1, l2b_Wih, l2b_bih, l2b_bhh, pxb, M_ROWS, G4, 2*HID);

    // 5) layer-2 recurrence
    init_kernel<<<256, 256>>>();
    recur_kernel<<<REC_BLOCKS, 256, SMEM_RECUR>>>(pxf, pxb, l2f_Whh, l2b_Whh, lengths, po2);

    // 6) classifier
    dim3 gc(1, M_ROWS/128);
    sgemm_db_kernel<<<gc, 256>>>(po2, cls_W, cls_b, nullptr, out, M_ROWS, NTAGS, 2*HID);
}

// round 5
// speedup vs baseline: 1.5358x; 1.4212x over previous
#include <cuda_runtime.h>
#include <cstdint>

#define BATCH 64
#define SEQ   512
#define EMB   128
#define HID   256
#define G4    1024            // 4*HID
#define NTAGS 50
#define M_ROWS (BATCH*SEQ)    // 32768
#define REC_BLOCKS 128        // 2 dirs * 32 j-slices * 2 batch-halves
#define GRP_BLOCKS 32         // blocks per (dir, bhalf) barrier group

// ---------------- scratch (device globals; allocation-free) ----------------
__device__ float g_x   [(size_t)M_ROWS*EMB];      // embedded input  [B*T, E]
__device__ float g_xg_f[(size_t)M_ROWS*G4];       // fwd gate pre-acts
__device__ float g_xg_b[(size_t)M_ROWS*G4];       // bwd gate pre-acts
__device__ float g_o1  [(size_t)M_ROWS*2*HID];    // layer1 output [B*T, 2H]
__device__ float g_o2  [(size_t)M_ROWS*2*HID];    // layer2 output
__device__ float g_h1  [2][2][HID][BATCH];        // layer1 h double buffer [parity][dir][k][b]
__device__ float g_h2  [2][2][HID][BATCH];        // layer2 h double buffer
__device__ int   g_bar [2][SEQ][4][8];            // [layer][step][group][pad] arrival counters

// ---------------- helpers ----------------
__device__ __forceinline__ int ld_acquire(const int* p) {
    int v;
    asm volatile("ld.global.acquire.gpu.b32 %0, [%1];" : "=r"(v) : "l"(p));
    return v;
}
__device__ __forceinline__ void red_release_add(int* p, int v) {
    asm volatile("red.release.gpu.global.add.u32 [%0], %1;" :: "l"(p), "r"(v) : "memory");
}
__device__ __forceinline__ float sigf(float x)  { return 1.f/(1.f + __expf(-x)); }
__device__ __forceinline__ float tanhf_(float x){ return 1.f - 2.f/(__expf(2.f*x) + 1.f); }

// ---------------- one-time per-replay state reset (launch #1) ----------------
__global__ void init_kernel() {
    int i = blockIdx.x * blockDim.x + threadIdx.x;    // 65536 threads
    if (i < 2*2*HID*BATCH) {
        (&g_h1[0][0][0][0])[i] = 0.f;
        (&g_h2[0][0][0][0])[i] = 0.f;
    }
    if (i < 2*SEQ*4*8) (&g_bar[0][0][0][0])[i] = 0;
}

// ---------------- embedding gather ----------------
__global__ void embed_kernel(const int* __restrict__ words, const float* __restrict__ emb) {
    int row = blockIdx.x * 8 + (threadIdx.x >> 5);    // 4096 blocks x 8 rows
    int lane = threadIdx.x & 31;
    int w = words[row];
    const float4* src = (const float4*)(emb + (size_t)w * EMB);
    float4*       dst = (float4*)(g_x + (size_t)row * EMB);
    dst[lane] = src[lane];
}

// ---------------- dual double-buffered SGEMM over blockIdx.z (fwd/bwd) ----------------
// C[M,N] = A[M,K]*Bw[N,K]^T + bias1 (+bias2). Requires M%128==0, K%16==0. N guarded.
__global__ __launch_bounds__(256) void sgemm_dual_kernel(
    const float* __restrict__ A,
    const float* __restrict__ Bw_f, const float* __restrict__ Bw_b,
    const float* __restrict__ b1f, const float* __restrict__ b2f,
    const float* __restrict__ b1b, const float* __restrict__ b2b,
    float* __restrict__ Cf, float* __restrict__ Cb,
    int M, int N, int K)
{
    const float* Bw    = blockIdx.z ? Bw_b : Bw_f;
    const float* bias1 = blockIdx.z ? b1b  : b1f;
    const float* bias2 = blockIdx.z ? b2b  : b2f;
    float*       C     = blockIdx.z ? Cb   : Cf;

    const int BM = 128, BN = 128, BK = 16;
    __shared__ float As[2][BK][BM];
    __shared__ float Bs[2][BK][BN];

    const int tid = threadIdx.x;
    const int m0 = blockIdx.y * BM;
    const int n0 = blockIdx.x * BN;
    const int ty = tid >> 4;          // 0..15
    const int tx = tid & 15;          // 0..15

    const int lr = tid >> 2;          // 0..63
    const int lk = (tid & 3) * 4;     // 0,4,8,12
    const float* Aptr0 = A + (size_t)(m0 + lr)      * K + lk;
    const float* Aptr1 = A + (size_t)(m0 + 64 + lr) * K + lk;
    const int bn0 = n0 + lr, bn1 = n0 + 64 + lr;
    const float* Bptr0 = Bw + (size_t)bn0 * K + lk;
    const float* Bptr1 = Bw + (size_t)bn1 * K + lk;
    const bool b0ok = bn0 < N, b1ok = bn1 < N;

    float acc[8][8];
    #pragma unroll
    for (int i = 0; i < 8; i++)
        #pragma unroll
        for (int j = 0; j < 8; j++) acc[i][j] = 0.f;

    const float4 z4 = make_float4(0.f,0.f,0.f,0.f);
    float4 av0, av1, bv0, bv1;

    av0 = *(const float4*)Aptr0;
    av1 = *(const float4*)Aptr1;
    bv0 = b0ok ? *(const float4*)Bptr0 : z4;
    bv1 = b1ok ? *(const float4*)Bptr1 : z4;
    As[0][lk+0][lr] = av0.x; As[0][lk+1][lr] = av0.y; As[0][lk+2][lr] = av0.z; As[0][lk+3][lr] = av0.w;
    As[0][lk+0][64+lr] = av1.x; As[0][lk+1][64+lr] = av1.y; As[0][lk+2][64+lr] = av1.z; As[0][lk+3][64+lr] = av1.w;
    Bs[0][lk+0][lr] = bv0.x; Bs[0][lk+1][lr] = bv0.y; Bs[0][lk+2][lr] = bv0.z; Bs[0][lk+3][lr] = bv0.w;
    Bs[0][lk+0][64+lr] = bv1.x; Bs[0][lk+1][64+lr] = bv1.y; Bs[0][lk+2][64+lr] = bv1.z; Bs[0][lk+3][64+lr] = bv1.w;
    __syncthreads();

    const int T = K / BK;
    for (int tI = 0; tI < T; tI++) {
        const int buf = tI & 1;
        const bool more = (tI + 1 < T);
        if (more) {
            const int off = (tI + 1) * BK;
            av0 = *(const float4*)(Aptr0 + off);
            av1 = *(const float4*)(Aptr1 + off);
            bv0 = b0ok ? *(const float4*)(Bptr0 + off) : z4;
            bv1 = b1ok ? *(const float4*)(Bptr1 + off) : z4;
        }
        #pragma unroll
        for (int k = 0; k < BK; k++) {
            float4 a0 = *(const float4*)&As[buf][k][ty*8];
            float4 a1 = *(const float4*)&As[buf][k][ty*8+4];
            float4 b0 = *(const float4*)&Bs[buf][k][tx*8];
            float4 b1 = *(const float4*)&Bs[buf][k][tx*8+4];
            float ar[8] = {a0.x,a0.y,a0.z,a0.w,a1.x,a1.y,a1.z,a1.w};
            float br[8] = {b0.x,b0.y,b0.z,b0.w,b1.x,b1.y,b1.z,b1.w};
            #pragma unroll
            for (int i = 0; i < 8; i++)
                #pragma unroll
                for (int j = 0; j < 8; j++)
                    acc[i][j] = fmaf(ar[i], br[j], acc[i][j]);
        }
        if (more) {
            const int nb = buf ^ 1;
            __syncthreads();
            As[nb][lk+0][lr] = av0.x; As[nb][lk+1][lr] = av0.y; As[nb][lk+2][lr] = av0.z; As[nb][lk+3][lr] = av0.w;
            As[nb][lk+0][64+lr] = av1.x; As[nb][lk+1][64+lr] = av1.y; As[nb][lk+2][64+lr] = av1.z; As[nb][lk+3][64+lr] = av1.w;
            Bs[nb][lk+0][lr] = bv0.x; Bs[nb][lk+1][lr] = bv0.y; Bs[nb][lk+2][lr] = bv0.z; Bs[nb][lk+3][lr] = bv0.w;
            Bs[nb][lk+0][64+lr] = bv1.x; Bs[nb][lk+1][64+lr] = bv1.y; Bs[nb][lk+2][64+lr] = bv1.z; Bs[nb][lk+3][64+lr] = bv1.w;
            __syncthreads();
        }
    }

    #pragma unroll
    for (int i = 0; i < 8; i++) {
        int m = m0 + ty*8 + i;
        #pragma unroll
        for (int j = 0; j < 8; j++) {
            int n = n0 + tx*8 + j;
            if (n < N) {
                float v = acc[i][j] + bias1[n] + (bias2 ? bias2[n] : 0.f);
                C[(size_t)m * N + n] = v;
            }
        }
    }
}

// ---------------- persistent BiLSTM recurrence, register-tiled ----------------
// 128 blocks = dir(2) x jslice(32) x bhalf(2). Per block: 32 gate-rows (4g x 8jj) x 32 batch.
// Thread decomposition: 4 k-groups x (8 r-tiles x 8 b-tiles), 4x4 register tile each.
// SMEM floats: w[256][32]=8192, h[256][32]=8192, part[4][32][32]=4096, xg[32][33]=1056,
//              hst[8][32]=256, lens 32  -> 21824 floats = 87296 B
#define SMEM_RECUR (21824 * 4)

__global__ __launch_bounds__(256, 1) void recur_kernel(
    const float* __restrict__ xg_f, const float* __restrict__ xg_b,
    const float* __restrict__ Whh_f, const float* __restrict__ Whh_b,
    const int* __restrict__ lengths, float* __restrict__ out,
    float* __restrict__ hbuf, int* __restrict__ bar)
{
    extern __shared__ float smem[];
    float* w_sm   = smem;                  // [256 k][32 r]   r = g*8+jj
    float* h_sm   = smem + 8192;           // [256 k][32 b]
    float* part   = smem + 16384;          // [4 kg][32 r][32 b]
    float* xg_sm  = smem + 20480;          // [32 b][33]  (g*8 + jj packed in 32, pad 1)
    float* hst    = smem + 21536;          // [8 jj][32 b]
    int*   lens_sm= (int*)(smem + 21792);  // [32]

    const int tid = threadIdx.x;
    const int blk = blockIdx.x;
    const int dir    = blk >> 6;
    const int jslice = (blk >> 1) & 31;
    const int bh     = blk & 1;
    const int j0 = jslice * 8;
    const int b0 = bh * 32;
    const int grp = dir * 2 + bh;          // barrier group (32 blocks each)
    const float* Whh = dir ? Whh_b : Whh_f;
    const float* xg  = dir ? xg_b  : xg_f;

    // one-time Whh slice load: w_sm[k][r] = Whh[g*HID + j0 + jj][k],  r = g*8+jj
    for (int idx = tid; idx < 8192; idx += 256) {
        int r = idx >> 8;         // 0..31
        int k = idx & 255;
        int g = r >> 3, jj = r & 7;
        w_sm[k*32 + r] = Whh[(size_t)(g*HID + j0 + jj) * HID + k];
    }
    if (tid < 32) lens_sm[tid] = lengths[b0 + tid];

    // compute-phase mapping
    const int kg = tid >> 6;               // 0..3 k-group (64 k each)
    const int ty = (tid >> 3) & 7;         // 0..7 r-tile (rows ty*4..+3)
    const int tx = tid & 7;                // 0..7 b-tile (batch tx*4..+3)

    // xg staging mapping: thread stages one float4 per step
    const int sb   = tid >> 3;             // 0..31 batch
    const int sg   = (tid >> 1) & 3;       // 0..3 gate
    const int shalf= tid & 1;              // 0..1
    const size_t xg_row_base = ((size_t)(b0 + sb) * SEQ);
    const int xg_col = sg*HID + j0 + shalf*4;

    // combine-phase mapping
    const int rr = tid >> 5;               // 0..7 = jj
    const int cb = tid & 31;               // 0..31 batch
    float c_reg = 0.f;

    __syncthreads();

    // prologue xg prefetch
    int t0 = dir ? (SEQ - 1) : 0;
    float4 xg_pf = __ldg((const float4*)(xg + (xg_row_base + t0) * G4 + xg_col));

    for (int s = 0; s < SEQ; s++) {
        const int t = dir ? (SEQ - 1 - s) : s;

        if (s > 0) {
            if (tid == 0) {
                int* cnt = bar + ((s-1)*4 + grp)*8;
                while (ld_acquire(cnt) < GRP_BLOCKS) __nanosleep(32);
            }
            __syncthreads();
        }

        // store staged xg, stage h_prev from L2, prefetch next xg
        {
            float* xd = xg_sm + sb*33 + sg*8 + shalf*4;
            xd[0] = xg_pf.x; xd[1] = xg_pf.y; xd[2] = xg_pf.z; xd[3] = xg_pf.w;

            const float* hsrc = hbuf + (size_t)((s & 1)*2 + dir) * HID * BATCH;
            #pragma unroll
            for (int n = 0; n < 8; n++) {
                int i = tid + n*256;               // 0..2047
                int k = i >> 3, o = (i & 7)*4;
                float4 v = __ldcg((const float4*)(hsrc + k*BATCH + b0 + o));
                *(float4*)(h_sm + k*32 + o) = v;
            }

            if (s + 1 < SEQ) {
                int tn = dir ? (SEQ - 2 - s) : (s + 1);
                xg_pf = __ldg((const float4*)(xg + (xg_row_base + tn) * G4 + xg_col));
            }
        }
        __syncthreads();

        // register-tiled partial GEMM: part[kg][r][b] over k in [kg*64, kg*64+64)
        {
            float acc[4][4];
            #pragma unroll
            for (int i = 0; i < 4; i++)
                #pragma unroll
                for (int j = 0; j < 4; j++) acc[i][j] = 0.f;

            const float* wp = w_sm + ty*4;
            const float* hp = h_sm + tx*4;
            #pragma unroll 4
            for (int kk = 0; kk < 64; kk++) {
                int k = kg*64 + kk;
                float4 wv = *(const float4*)(wp + k*32);
                float4 hv = *(const float4*)(hp + k*32);
                float wa[4] = {wv.x, wv.y, wv.z, wv.w};
                float ha[4] = {hv.x, hv.y, hv.z, hv.w};
                #pragma unroll
                for (int i = 0; i < 4; i++)
                    #pragma unroll
                    for (int j = 0; j < 4; j++)
                        acc[i][j] = fmaf(wa[i], ha[j], acc[i][j]);
            }
            float* pd = part + kg*1024 + (ty*4)*32 + tx*4;
            #pragma unroll
            for (int i = 0; i < 4; i++)
                *(float4*)(pd + i*32) = make_float4(acc[i][0], acc[i][1], acc[i][2], acc[i][3]);
        }
        __syncthreads();

        // reduce partials + xg, activations, c/h update (thread = (jj=rr, b=cb))
        {
            float gate[4];
            #pragma unroll
            for (int g = 0; g < 4; g++) {
                int r = g*8 + rr;
                float v = part[0*1024 + r*32 + cb] + part[1*1024 + r*32 + cb]
                        + part[2*1024 + r*32 + cb] + part[3*1024 + r*32 + cb];
                gate[g] = v + xg_sm[cb*33 + g*8 + rr];
            }
            float c_new = sigf(gate[1]) * c_reg + sigf(gate[0]) * tanhf_(gate[2]);
            float h_new = sigf(gate[3]) * tanhf_(c_new);
            float h_prev = h_sm[(j0 + rr)*32 + cb];
            bool  m = (t < lens_sm[cb]);
            float h_out = m ? h_new : h_prev;
            c_reg       = m ? c_new : c_reg;

            hbuf[(size_t)(((s+1) & 1)*2 + dir) * HID * BATCH + (j0 + rr)*BATCH + b0 + cb] = h_out;
            hst[rr*32 + cb] = h_out;
        }
        __syncthreads();
        if (tid == 0) red_release_add(bar + (s*4 + grp)*8, 1);

        // semi-coalesced out store (64 threads x float4)
        if (tid < 64) {
            int bb  = tid >> 1;
            int seg = tid & 1;
            float4 v;
            v.x = hst[(seg*4+0)*32 + bb];
            v.y = hst[(seg*4+1)*32 + bb];
            v.z = hst[(seg*4+2)*32 + bb];
            v.w = hst[(seg*4+3)*32 + bb];
            *(float4*)(out + ((size_t)(b0 + bb) * SEQ + t) * (2*HID) + dir*HID + j0 + seg*4) = v;
        }
    }
}

// ---------------- launch ----------------
extern "C" void kernel_launch(void* const* d_in, const int* in_sizes, int n_in,
                              void* d_out, int out_size)
{
    (void)in_sizes; (void)n_in; (void)out_size;
    const int*   words    = (const int*)  d_in[0];
    const int*   lengths  = (const int*)  d_in[1];
    const float* emb      = (const float*)d_in[2];
    const float* l1f_Wih  = (const float*)d_in[3];
    const float* l1f_Whh  = (const float*)d_in[4];
    const float* l1f_bih  = (const float*)d_in[5];
    const float* l1f_bhh  = (const float*)d_in[6];
    const float* l1b_Wih  = (const float*)d_in[7];
    const float* l1b_Whh  = (const float*)d_in[8];
    const float* l1b_bih  = (const float*)d_in[9];
    const float* l1b_bhh  = (const float*)d_in[10];
    const float* l2f_Wih  = (const float*)d_in[11];
    const float* l2f_Whh  = (const float*)d_in[12];
    const float* l2f_bih  = (const float*)d_in[13];
    const float* l2f_bhh  = (const float*)d_in[14];
    const float* l2b_Wih  = (const float*)d_in[15];
    const float* l2b_Whh  = (const float*)d_in[16];
    const float* l2b_bih  = (const float*)d_in[17];
    const float* l2b_bhh  = (const float*)d_in[18];
    const float* cls_W    = (const float*)d_in[19];
    const float* cls_b    = (const float*)d_in[20];
    float* out = (float*)d_out;

    float *px, *pxf, *pxb, *po1, *po2, *ph1, *ph2;
    int *pbar;
    cudaGetSymbolAddress((void**)&px,   g_x);
    cudaGetSymbolAddress((void**)&pxf,  g_xg_f);
    cudaGetSymbolAddress((void**)&pxb,  g_xg_b);
    cudaGetSymbolAddress((void**)&po1,  g_o1);
    cudaGetSymbolAddress((void**)&po2,  g_o2);
    cudaGetSymbolAddress((void**)&ph1,  g_h1);
    cudaGetSymbolAddress((void**)&ph2,  g_h2);
    cudaGetSymbolAddress((void**)&pbar, g_bar);

    cudaFuncSetAttribute(recur_kernel, cudaFuncAttributeMaxDynamicSharedMemorySize, SMEM_RECUR);

    // 1) init all barriers + h buffers
    init_kernel<<<256, 256>>>();

    // 2) embedding
    embed_kernel<<<M_ROWS/8, 256>>>(words, emb);

    // 3) layer-1 input projections (f+b fused over z)
    dim3 gx(G4/128, M_ROWS/128, 2);
    sgemm_dual_kernel<<<gx, 256>>>(px, l1f_Wih, l1b_Wih,
                                   l1f_bih, l1f_bhh, l1b_bih, l1b_bhh,
                                   pxf, pxb, M_ROWS, G4, EMB);

    // 4) layer-1 recurrence
    recur_kernel<<<REC_BLOCKS, 256, SMEM_RECUR>>>(pxf, pxb, l1f_Whh, l1b_Whh,
                                                  lengths, po1, ph1, pbar);

    // 5) layer-2 input projections
    sgemm_dual_kernel<<<gx, 256>>>(po1, l2f_Wih, l2b_Wih,
                                   l2f_bih, l2f_bhh, l2b_bih, l2b_bhh,
                                   pxf, pxb, M_ROWS, G4, 2*HID);

    // 6) layer-2 recurrence
    recur_kernel<<<REC_BLOCKS, 256, SMEM_RECUR>>>(pxf, pxb, l2f_Whh, l2b_Whh,
                                                  lengths, po2, ph2, pbar + SEQ*4*8);

    // 7) classifier
    dim3 gc(1, M_ROWS/128, 1);
    sgemm_dual_kernel<<<gc, 256>>>(po2, cls_W, cls_W,
                                   cls_b, nullptr, cls_b, nullptr,
                                   out, out, M_ROWS, NTAGS, 2*HID);
}

// round 6
// speedup vs baseline: 2.0630x; 1.3433x over previous
#include <cuda_runtime.h>
#include <cstdint>

#define BATCH 64
#define SEQ   512
#define EMB   128
#define HID   256
#define G4    1024            // 4*HID
#define NTAGS 50
#define M_ROWS (BATCH*SEQ)    // 32768
#define REC_BLOCKS 128        // 2 dirs * 32 j-slices * 2 batch-halves
#define GRP_BLOCKS 32         // blocks per (dir, bhalf) barrier group

// ---------------- scratch (device globals; allocation-free) ----------------
__device__ float g_x   [(size_t)M_ROWS*EMB];      // embedded input  [B*T, E]
__device__ float g_xg_f[(size_t)M_ROWS*G4];       // fwd gate pre-acts
__device__ float g_xg_b[(size_t)M_ROWS*G4];       // bwd gate pre-acts
__device__ float g_o1  [(size_t)M_ROWS*2*HID];    // layer1 output [B*T, 2H]
__device__ float g_o2  [(size_t)M_ROWS*2*HID];    // layer2 output
__device__ float g_h1  [2][2][HID][BATCH];        // layer1 h double buffer [parity][dir][k][b]
__device__ float g_h2  [2][2][HID][BATCH];        // layer2 h double buffer
__device__ int   g_bar [2][SEQ][4][8];            // [layer][step][group][pad] arrival counters

// ---------------- helpers ----------------
__device__ __forceinline__ int ld_acquire(const int* p) {
    int v;
    asm volatile("ld.global.acquire.gpu.b32 %0, [%1];" : "=r"(v) : "l"(p));
    return v;
}
__device__ __forceinline__ void red_release_add(int* p, int v) {
    asm volatile("red.release.gpu.global.add.u32 [%0], %1;" :: "l"(p), "r"(v) : "memory");
}
__device__ __forceinline__ float sigf(float x)  { return 1.f/(1.f + __expf(-x)); }
__device__ __forceinline__ float tanhf_(float x){ return 1.f - 2.f/(__expf(2.f*x) + 1.f); }
__device__ __forceinline__ uint32_t f2tf32(float f) {
    uint32_t u;
    asm("cvt.rna.tf32.f32 %0, %1;" : "=r"(u) : "f"(f));
    return u;
}
__device__ __forceinline__ void mma_tf32(float& c0, float& c1, float& c2, float& c3,
                                         uint32_t a0, uint32_t a1, uint32_t a2, uint32_t a3,
                                         uint32_t b0, uint32_t b1) {
    asm volatile("mma.sync.aligned.m16n8k8.row.col.f32.tf32.tf32.f32 "
                 "{%0,%1,%2,%3}, {%4,%5,%6,%7}, {%8,%9}, {%0,%1,%2,%3};"
                 : "+f"(c0), "+f"(c1), "+f"(c2), "+f"(c3)
                 : "r"(a0), "r"(a1), "r"(a2), "r"(a3), "r"(b0), "r"(b1));
}

// ---------------- one-time per-replay state reset ----------------
__global__ void init_kernel() {
    int i = blockIdx.x * blockDim.x + threadIdx.x;
    if (i < 2*2*HID*BATCH) {
        (&g_h1[0][0][0][0])[i] = 0.f;
        (&g_h2[0][0][0][0])[i] = 0.f;
    }
    if (i < 2*SEQ*4*8) (&g_bar[0][0][0][0])[i] = 0;
}

// ---------------- embedding gather ----------------
__global__ void embed_kernel(const int* __restrict__ words, const float* __restrict__ emb) {
    int row = blockIdx.x * 8 + (threadIdx.x >> 5);
    int lane = threadIdx.x & 31;
    int w = words[row];
    const float4* src = (const float4*)(emb + (size_t)w * EMB);
    float4*       dst = (float4*)(g_x + (size_t)row * EMB);
    dst[lane] = src[lane];
}

// ---------------- tf32 tensor-core dual GEMM:  C[M,N] = A[M,K]*Bw[N,K]^T + bias1 + bias2 ----
// 128x128 block tile, 8 warps (2m x 4n), warp tile 64x32 (4x4 m16n8k8 atoms), BK=16, db smem.
// Requires M%128==0, N%128==0, K%16==0.
__global__ __launch_bounds__(256) void gemm_tf32_dual(
    const float* __restrict__ A,
    const float* __restrict__ Bw_f, const float* __restrict__ Bw_b,
    const float* __restrict__ b1f, const float* __restrict__ b2f,
    const float* __restrict__ b1b, const float* __restrict__ b2b,
    float* __restrict__ Cf, float* __restrict__ Cb,
    int M, int N, int K)
{
    const float* Bw    = blockIdx.z ? Bw_b : Bw_f;
    const float* bias1 = blockIdx.z ? b1b  : b1f;
    const float* bias2 = blockIdx.z ? b2b  : b2f;
    float*       C     = blockIdx.z ? Cb   : Cf;

    __shared__ uint32_t As[2][128][20];   // [buf][m][k] tf32, pad to 20 for bank-free frags
    __shared__ uint32_t Bs[2][128][20];   // [buf][n][k]

    const int tid  = threadIdx.x;
    const int lane = tid & 31;
    const int warp = tid >> 5;
    const int m0 = blockIdx.y * 128;
    const int n0 = blockIdx.x * 128;
    const int wm = (warp >> 2) * 64;      // warp m offset (0/64)
    const int wn = (warp & 3) * 32;       // warp n offset (0..96)
    const int ar = lane >> 2;             // fragment row base 0..7
    const int ac = lane & 3;              // fragment col base 0..3

    // loader mapping: rows lr, lr+64; k cols lk..lk+3
    const int lr = tid >> 2;
    const int lk = (tid & 3) * 4;
    const float* Aptr0 = A  + (size_t)(m0 + lr)      * K + lk;
    const float* Aptr1 = A  + (size_t)(m0 + 64 + lr) * K + lk;
    const float* Bptr0 = Bw + (size_t)(n0 + lr)      * K + lk;
    const float* Bptr1 = Bw + (size_t)(n0 + 64 + lr) * K + lk;

    float c[4][4][4];
    #pragma unroll
    for (int i = 0; i < 4; i++)
        #pragma unroll
        for (int j = 0; j < 4; j++)
            #pragma unroll
            for (int r = 0; r < 4; r++) c[i][j][r] = 0.f;

    // prologue: tile 0 -> buf 0
    {
        float4 a0 = *(const float4*)Aptr0;
        float4 a1 = *(const float4*)Aptr1;
        float4 b0 = *(const float4*)Bptr0;
        float4 b1 = *(const float4*)Bptr1;
        As[0][lr][lk+0]=f2tf32(a0.x); As[0][lr][lk+1]=f2tf32(a0.y); As[0][lr][lk+2]=f2tf32(a0.z); As[0][lr][lk+3]=f2tf32(a0.w);
        As[0][64+lr][lk+0]=f2tf32(a1.x); As[0][64+lr][lk+1]=f2tf32(a1.y); As[0][64+lr][lk+2]=f2tf32(a1.z); As[0][64+lr][lk+3]=f2tf32(a1.w);
        Bs[0][lr][lk+0]=f2tf32(b0.x); Bs[0][lr][lk+1]=f2tf32(b0.y); Bs[0][lr][lk+2]=f2tf32(b0.z); Bs[0][lr][lk+3]=f2tf32(b0.w);
        Bs[0][64+lr][lk+0]=f2tf32(b1.x); Bs[0][64+lr][lk+1]=f2tf32(b1.y); Bs[0][64+lr][lk+2]=f2tf32(b1.z); Bs[0][64+lr][lk+3]=f2tf32(b1.w);
    }
    __syncthreads();

    const int T = K / 16;
    float4 pa0, pa1, pb0, pb1;
    for (int tI = 0; tI < T; tI++) {
        const int buf = tI & 1;
        const bool more = (tI + 1 < T);
        if (more) {
            const int off = (tI + 1) * 16;
            pa0 = *(const float4*)(Aptr0 + off);
            pa1 = *(const float4*)(Aptr1 + off);
            pb0 = *(const float4*)(Bptr0 + off);
            pb1 = *(const float4*)(Bptr1 + off);
        }

        #pragma unroll
        for (int kb = 0; kb < 16; kb += 8) {
            uint32_t afr[4][4];
            #pragma unroll
            for (int i = 0; i < 4; i++) {
                int mrow = wm + i*16 + ar;
                afr[i][0] = As[buf][mrow    ][kb + ac];
                afr[i][1] = As[buf][mrow + 8][kb + ac];
                afr[i][2] = As[buf][mrow    ][kb + ac + 4];
                afr[i][3] = As[buf][mrow + 8][kb + ac + 4];
            }
            uint32_t bfr[4][2];
            #pragma unroll
            for (int j = 0; j < 4; j++) {
                int nrow = wn + j*8 + ar;
                bfr[j][0] = Bs[buf][nrow][kb + ac];
                bfr[j][1] = Bs[buf][nrow][kb + ac + 4];
            }
            #pragma unroll
            for (int i = 0; i < 4; i++)
                #pragma unroll
                for (int j = 0; j < 4; j++)
                    mma_tf32(c[i][j][0], c[i][j][1], c[i][j][2], c[i][j][3],
                             afr[i][0], afr[i][1], afr[i][2], afr[i][3],
                             bfr[j][0], bfr[j][1]);
        }

        if (more) {
            const int nb = buf ^ 1;
            __syncthreads();
            As[nb][lr][lk+0]=f2tf32(pa0.x); As[nb][lr][lk+1]=f2tf32(pa0.y); As[nb][lr][lk+2]=f2tf32(pa0.z); As[nb][lr][lk+3]=f2tf32(pa0.w);
            As[nb][64+lr][lk+0]=f2tf32(pa1.x); As[nb][64+lr][lk+1]=f2tf32(pa1.y); As[nb][64+lr][lk+2]=f2tf32(pa1.z); As[nb][64+lr][lk+3]=f2tf32(pa1.w);
            Bs[nb][lr][lk+0]=f2tf32(pb0.x); Bs[nb][lr][lk+1]=f2tf32(pb0.y); Bs[nb][lr][lk+2]=f2tf32(pb0.z); Bs[nb][lr][lk+3]=f2tf32(pb0.w);
            Bs[nb][64+lr][lk+0]=f2tf32(pb1.x); Bs[nb][64+lr][lk+1]=f2tf32(pb1.y); Bs[nb][64+lr][lk+2]=f2tf32(pb1.z); Bs[nb][64+lr][lk+3]=f2tf32(pb1.w);
            __syncthreads();
        }
    }

    // epilogue: c[i][j] -> C with bias (float2 stores; cols are even-aligned pairs)
    #pragma unroll
    for (int i = 0; i < 4; i++) {
        int row0 = m0 + wm + i*16 + ar;
        #pragma unroll
        for (int j = 0; j < 4; j++) {
            int col = n0 + wn + j*8 + 2*ac;
            float bsum0 = bias1[col]   + (bias2 ? bias2[col]   : 0.f);
            float bsum1 = bias1[col+1] + (bias2 ? bias2[col+1] : 0.f);
            *(float2*)(C + (size_t)row0 * N + col)       = make_float2(c[i][j][0] + bsum0, c[i][j][1] + bsum1);
            *(float2*)(C + (size_t)(row0 + 8) * N + col) = make_float2(c[i][j][2] + bsum0, c[i][j][3] + bsum1);
        }
    }
}

// ---------------- fp32 SIMT GEMM (classifier only: N=50) ----------------
__global__ __launch_bounds__(256) void sgemm_cls_kernel(
    const float* __restrict__ A, const float* __restrict__ Bw,
    const float* __restrict__ bias1,
    float* __restrict__ C, int M, int N, int K)
{
    const int BM = 128, BN = 128, BK = 16;
    __shared__ float As[2][BK][BM];
    __shared__ float Bs[2][BK][BN];

    const int tid = threadIdx.x;
    const int m0 = blockIdx.y * BM;
    const int n0 = blockIdx.x * BN;
    const int ty = tid >> 4;
    const int tx = tid & 15;

    const int lr = tid >> 2;
    const int lk = (tid & 3) * 4;
    const float* Aptr0 = A + (size_t)(m0 + lr)      * K + lk;
    const float* Aptr1 = A + (size_t)(m0 + 64 + lr) * K + lk;
    const int bn0 = n0 + lr, bn1 = n0 + 64 + lr;
    const float* Bptr0 = Bw + (size_t)bn0 * K + lk;
    const float* Bptr1 = Bw + (size_t)bn1 * K + lk;
    const bool b0ok = bn0 < N, b1ok = bn1 < N;

    float acc[8][8];
    #pragma unroll
    for (int i = 0; i < 8; i++)
        #pragma unroll
        for (int j = 0; j < 8; j++) acc[i][j] = 0.f;

    const float4 z4 = make_float4(0.f,0.f,0.f,0.f);
    float4 av0, av1, bv0, bv1;

    av0 = *(const float4*)Aptr0;
    av1 = *(const float4*)Aptr1;
    bv0 = b0ok ? *(const float4*)Bptr0 : z4;
    bv1 = b1ok ? *(const float4*)Bptr1 : z4;
    As[0][lk+0][lr] = av0.x; As[0][lk+1][lr] = av0.y; As[0][lk+2][lr] = av0.z; As[0][lk+3][lr] = av0.w;
    As[0][lk+0][64+lr] = av1.x; As[0][lk+1][64+lr] = av1.y; As[0][lk+2][64+lr] = av1.z; As[0][lk+3][64+lr] = av1.w;
    Bs[0][lk+0][lr] = bv0.x; Bs[0][lk+1][lr] = bv0.y; Bs[0][lk+2][lr] = bv0.z; Bs[0][lk+3][lr] = bv0.w;
    Bs[0][lk+0][64+lr] = bv1.x; Bs[0][lk+1][64+lr] = bv1.y; Bs[0][lk+2][64+lr] = bv1.z; Bs[0][lk+3][64+lr] = bv1.w;
    __syncthreads();

    const int T = K / BK;
    for (int tI = 0; tI < T; tI++) {
        const int buf = tI & 1;
        const bool more = (tI + 1 < T);
        if (more) {
            const int off = (tI + 1) * BK;
            av0 = *(const float4*)(Aptr0 + off);
            av1 = *(const float4*)(Aptr1 + off);
            bv0 = b0ok ? *(const float4*)(Bptr0 + off) : z4;
            bv1 = b1ok ? *(const float4*)(Bptr1 + off) : z4;
        }
        #pragma unroll
        for (int k = 0; k < BK; k++) {
            float4 a0 = *(const float4*)&As[buf][k][ty*8];
            float4 a1 = *(const float4*)&As[buf][k][ty*8+4];
            float4 b0 = *(const float4*)&Bs[buf][k][tx*8];
            float4 b1 = *(const float4*)&Bs[buf][k][tx*8+4];
            float ar[8] = {a0.x,a0.y,a0.z,a0.w,a1.x,a1.y,a1.z,a1.w};
            float br[8] = {b0.x,b0.y,b0.z,b0.w,b1.x,b1.y,b1.z,b1.w};
            #pragma unroll
            for (int i = 0; i < 8; i++)
                #pragma unroll
                for (int j = 0; j < 8; j++)
                    acc[i][j] = fmaf(ar[i], br[j], acc[i][j]);
        }
        if (more) {
            const int nb = buf ^ 1;
            __syncthreads();
            As[nb][lk+0][lr] = av0.x; As[nb][lk+1][lr] = av0.y; As[nb][lk+2][lr] = av0.z; As[nb][lk+3][lr] = av0.w;
            As[nb][lk+0][64+lr] = av1.x; As[nb][lk+1][64+lr] = av1.y; As[nb][lk+2][64+lr] = av1.z; As[nb][lk+3][64+lr] = av1.w;
            Bs[nb][lk+0][lr] = bv0.x; Bs[nb][lk+1][lr] = bv0.y; Bs[nb][lk+2][lr] = bv0.z; Bs[nb][lk+3][lr] = bv0.w;
            Bs[nb][lk+0][64+lr] = bv1.x; Bs[nb][lk+1][64+lr] = bv1.y; Bs[nb][lk+2][64+lr] = bv1.z; Bs[nb][lk+3][64+lr] = bv1.w;
            __syncthreads();
        }
    }

    #pragma unroll
    for (int i = 0; i < 8; i++) {
        int m = m0 + ty*8 + i;
        #pragma unroll
        for (int j = 0; j < 8; j++) {
            int n = n0 + tx*8 + j;
            if (n < N) C[(size_t)m * N + n] = acc[i][j] + bias1[n];
        }
    }
}

// ---------------- persistent BiLSTM recurrence, register-tiled (unchanged from R5) ----------
#define SMEM_RECUR (21824 * 4)

__global__ __launch_bounds__(256, 1) void recur_kernel(
    const float* __restrict__ xg_f, const float* __restrict__ xg_b,
    const float* __restrict__ Whh_f, const float* __restrict__ Whh_b,
    const int* __restrict__ lengths, float* __restrict__ out,
    float* __restrict__ hbuf, int* __restrict__ bar)
{
    extern __shared__ float smem[];
    float* w_sm   = smem;                  // [256 k][32 r]   r = g*8+jj
    float* h_sm   = smem + 8192;           // [256 k][32 b]
    float* part   = smem + 16384;          // [4 kg][32 r][32 b]
    float* xg_sm  = smem + 20480;          // [32 b][33]
    float* hst    = smem + 21536;          // [8 jj][32 b]
    int*   lens_sm= (int*)(smem + 21792);  // [32]

    const int tid = threadIdx.x;
    const int blk = blockIdx.x;
    const int dir    = blk >> 6;
    const int jslice = (blk >> 1) & 31;
    const int bh     = blk & 1;
    const int j0 = jslice * 8;
    const int b0 = bh * 32;
    const int grp = dir * 2 + bh;
    const float* Whh = dir ? Whh_b : Whh_f;
    const float* xg  = dir ? xg_b  : xg_f;

    for (int idx = tid; idx < 8192; idx += 256) {
        int r = idx >> 8;
        int k = idx & 255;
        int g = r >> 3, jj = r & 7;
        w_sm[k*32 + r] = Whh[(size_t)(g*HID + j0 + jj) * HID + k];
    }
    if (tid < 32) lens_sm[tid] = lengths[b0 + tid];

    const int kg = tid >> 6;
    const int ty = (tid >> 3) & 7;
    const int tx = tid & 7;

    const int sb   = tid >> 3;
    const int sg   = (tid >> 1) & 3;
    const int shalf= tid & 1;
    const size_t xg_row_base = ((size_t)(b0 + sb) * SEQ);
    const int xg_col = sg*HID + j0 + shalf*4;

    const int rr = tid >> 5;
    const int cb = tid & 31;
    float c_reg = 0.f;

    __syncthreads();

    int t0 = dir ? (SEQ - 1) : 0;
    float4 xg_pf = __ldg((const float4*)(xg + (xg_row_base + t0) * G4 + xg_col));

    for (int s = 0; s < SEQ; s++) {
        const int t = dir ? (SEQ - 1 - s) : s;

        if (s > 0) {
            if (tid == 0) {
                int* cnt = bar + ((s-1)*4 + grp)*8;
                while (ld_acquire(cnt) < GRP_BLOCKS) __nanosleep(32);
            }
            __syncthreads();
        }

        {
            float* xd = xg_sm + sb*33 + sg*8 + shalf*4;
            xd[0] = xg_pf.x; xd[1] = xg_pf.y; xd[2] = xg_pf.z; xd[3] = xg_pf.w;

            const float* hsrc = hbuf + (size_t)((s & 1)*2 + dir) * HID * BATCH;
            #pragma unroll
            for (int n = 0; n < 8; n++) {
                int i = tid + n*256;
                int k = i >> 3, o = (i & 7)*4;
                float4 v = __ldcg((const float4*)(hsrc + k*BATCH + b0 + o));
                *(float4*)(h_sm + k*32 + o) = v;
            }

            if (s + 1 < SEQ) {
                int tn = dir ? (SEQ - 2 - s) : (s + 1);
                xg_pf = __ldg((const float4*)(xg + (xg_row_base + tn) * G4 + xg_col));
            }
        }
        __syncthreads();

        {
            float acc[4][4];
            #pragma unroll
            for (int i = 0; i < 4; i++)
                #pragma unroll
                for (int j = 0; j < 4; j++) acc[i][j] = 0.f;

            const float* wp = w_sm + ty*4;
            const float* hp = h_sm + tx*4;
            #pragma unroll 4
            for (int kk = 0; kk < 64; kk++) {
                int k = kg*64 + kk;
                float4 wv = *(const float4*)(wp + k*32);
                float4 hv = *(const float4*)(hp + k*32);
                float wa[4] = {wv.x, wv.y, wv.z, wv.w};
                float ha[4] = {hv.x, hv.y, hv.z, hv.w};
                #pragma unroll
                for (int i = 0; i < 4; i++)
                    #pragma unroll
                    for (int j = 0; j < 4; j++)
                        acc[i][j] = fmaf(wa[i], ha[j], acc[i][j]);
            }
            float* pd = part + kg*1024 + (ty*4)*32 + tx*4;
            #pragma unroll
            for (int i = 0; i < 4; i++)
                *(float4*)(pd + i*32) = make_float4(acc[i][0], acc[i][1], acc[i][2], acc[i][3]);
        }
        __syncthreads();

        {
            float gate[4];
            #pragma unroll
            for (int g = 0; g < 4; g++) {
                int r = g*8 + rr;
                float v = part[0*1024 + r*32 + cb] + part[1*1024 + r*32 + cb]
                        + part[2*1024 + r*32 + cb] + part[3*1024 + r*32 + cb];
                gate[g] = v + xg_sm[cb*33 + g*8 + rr];
            }
            float c_new = sigf(gate[1]) * c_reg + sigf(gate[0]) * tanhf_(gate[2]);
            float h_new = sigf(gate[3]) * tanhf_(c_new);
            float h_prev = h_sm[(j0 + rr)*32 + cb];
            bool  m = (t < lens_sm[cb]);
            float h_out = m ? h_new : h_prev;
            c_reg       = m ? c_new : c_reg;

            hbuf[(size_t)(((s+1) & 1)*2 + dir) * HID * BATCH + (j0 + rr)*BATCH + b0 + cb] = h_out;
            hst[rr*32 + cb] = h_out;
        }
        __syncthreads();
        if (tid == 0) red_release_add(bar + (s*4 + grp)*8, 1);

        if (tid < 64) {
            int bb  = tid >> 1;
            int seg = tid & 1;
            float4 v;
            v.x = hst[(seg*4+0)*32 + bb];
            v.y = hst[(seg*4+1)*32 + bb];
            v.z = hst[(seg*4+2)*32 + bb];
            v.w = hst[(seg*4+3)*32 + bb];
            *(float4*)(out + ((size_t)(b0 + bb) * SEQ + t) * (2*HID) + dir*HID + j0 + seg*4) = v;
        }
    }
}

// ---------------- launch ----------------
extern "C" void kernel_launch(void* const* d_in, const int* in_sizes, int n_in,
                              void* d_out, int out_size)
{
    (void)in_sizes; (void)n_in; (void)out_size;
    const int*   words    = (const int*)  d_in[0];
    const int*   lengths  = (const int*)  d_in[1];
    const float* emb      = (const float*)d_in[2];
    const float* l1f_Wih  = (const float*)d_in[3];
    const float* l1f_Whh  = (const float*)d_in[4];
    const float* l1f_bih  = (const float*)d_in[5];
    const float* l1f_bhh  = (const float*)d_in[6];
    const float* l1b_Wih  = (const float*)d_in[7];
    const float* l1b_Whh  = (const float*)d_in[8];
    const float* l1b_bih  = (const float*)d_in[9];
    const float* l1b_bhh  = (const float*)d_in[10];
    const float* l2f_Wih  = (const float*)d_in[11];
    const float* l2f_Whh  = (const float*)d_in[12];
    const float* l2f_bih  = (const float*)d_in[13];
    const float* l2f_bhh  = (const float*)d_in[14];
    const float* l2b_Wih  = (const float*)d_in[15];
    const float* l2b_Whh  = (const float*)d_in[16];
    const float* l2b_bih  = (const float*)d_in[17];
    const float* l2b_bhh  = (const float*)d_in[18];
    const float* cls_W    = (const float*)d_in[19];
    const float* cls_b    = (const float*)d_in[20];
    float* out = (float*)d_out;

    float *px, *pxf, *pxb, *po1, *po2, *ph1, *ph2;
    int *pbar;
    cudaGetSymbolAddress((void**)&px,   g_x);
    cudaGetSymbolAddress((void**)&pxf,  g_xg_f);
    cudaGetSymbolAddress((void**)&pxb,  g_xg_b);
    cudaGetSymbolAddress((void**)&po1,  g_o1);
    cudaGetSymbolAddress((void**)&po2,  g_o2);
    cudaGetSymbolAddress((void**)&ph1,  g_h1);
    cudaGetSymbolAddress((void**)&ph2,  g_h2);
    cudaGetSymbolAddress((void**)&pbar, g_bar);

    cudaFuncSetAttribute(recur_kernel, cudaFuncAttributeMaxDynamicSharedMemorySize, SMEM_RECUR);

    // 1) init barriers + h buffers
    init_kernel<<<256, 256>>>();

    // 2) embedding
    embed_kernel<<<M_ROWS/8, 256>>>(words, emb);

    // 3) layer-1 input projections (tf32 tensor cores, f+b fused over z)
    dim3 gx(G4/128, M_ROWS/128, 2);
    gemm_tf32_dual<<<gx, 256>>>(px, l1f_Wih, l1b_Wih,
                                l1f_bih, l1f_bhh, l1b_bih, l1b_bhh,
                                pxf, pxb, M_ROWS, G4, EMB);

    // 4) layer-1 recurrence
    recur_kernel<<<REC_BLOCKS, 256, SMEM_RECUR>>>(pxf, pxb, l1f_Whh, l1b_Whh,
                                                  lengths, po1, ph1, pbar);

    // 5) layer-2 input projections
    gemm_tf32_dual<<<gx, 256>>>(po1, l2f_Wih, l2b_Wih,
                                l2f_bih, l2f_bhh, l2b_bih, l2b_bhh,
                                pxf, pxb, M_ROWS, G4, 2*HID);

    // 6) layer-2 recurrence
    recur_kernel<<<REC_BLOCKS, 256, SMEM_RECUR>>>(pxf, pxb, l2f_Whh, l2b_Whh,
                                                  lengths, po2, ph2, pbar + SEQ*4*8);

    // 7) classifier (fp32 for final-logit precision margin)
    dim3 gc(1, M_ROWS/128, 1);
    sgemm_cls_kernel<<<gc, 256>>>(po2, cls_W, cls_b, out, M_ROWS, NTAGS, 2*HID);
}

// round 7
// speedup vs baseline: 2.7877x; 1.3512x over previous
#include <cuda_runtime.h>
#include <cstdint>

#define BATCH 64
#define SEQ   512
#define EMB   128
#define HID   256
#define G4    1024            // 4*HID
#define NTAGS 50
#define M_ROWS (BATCH*SEQ)    // 32768
#define REC_BLOCKS 128        // 2 dirs * 32 j-slices * 2 batch-halves
#define GRP_BLOCKS 32         // blocks per (dir, bhalf) barrier group
#define HSTRIDE 40            // smem row stride (floats) for conflict-free B frags

// ---------------- scratch (device globals; allocation-free) ----------------
__device__ float g_x   [(size_t)M_ROWS*EMB];
__device__ float g_xg_f[(size_t)M_ROWS*G4];
__device__ float g_xg_b[(size_t)M_ROWS*G4];
__device__ float g_o1  [(size_t)M_ROWS*2*HID];
__device__ float g_o2  [(size_t)M_ROWS*2*HID];
__device__ float g_h1  [2][2][HID][BATCH];        // [parity][dir][k][b]
__device__ float g_h2  [2][2][HID][BATCH];
__device__ int   g_bar [2][SEQ][4][8];            // [layer][step][group][pad]

// ---------------- helpers ----------------
__device__ __forceinline__ int ld_acquire(const int* p) {
    int v;
    asm volatile("ld.global.acquire.gpu.b32 %0, [%1];" : "=r"(v) : "l"(p));
    return v;
}
__device__ __forceinline__ void red_release_add(int* p, int v) {
    asm volatile("red.release.gpu.global.add.u32 [%0], %1;" :: "l"(p), "r"(v) : "memory");
}
__device__ __forceinline__ float sigf(float x)  { return 1.f/(1.f + __expf(-x)); }
__device__ __forceinline__ float tanhf_(float x){ return 1.f - 2.f/(__expf(2.f*x) + 1.f); }
__device__ __forceinline__ uint32_t f2tf32(float f) {
    uint32_t u;
    asm("cvt.rna.tf32.f32 %0, %1;" : "=r"(u) : "f"(f));
    return u;
}
__device__ __forceinline__ void mma_tf32(float& c0, float& c1, float& c2, float& c3,
                                         uint32_t a0, uint32_t a1, uint32_t a2, uint32_t a3,
                                         uint32_t b0, uint32_t b1) {
    asm volatile("mma.sync.aligned.m16n8k8.row.col.f32.tf32.tf32.f32 "
                 "{%0,%1,%2,%3}, {%4,%5,%6,%7}, {%8,%9}, {%0,%1,%2,%3};"
                 : "+f"(c0), "+f"(c1), "+f"(c2), "+f"(c3)
                 : "r"(a0), "r"(a1), "r"(a2), "r"(a3), "r"(b0), "r"(b1));
}

// ---------------- init ----------------
__global__ void init_kernel() {
    int i = blockIdx.x * blockDim.x + threadIdx.x;
    if (i < 2*2*HID*BATCH) {
        (&g_h1[0][0][0][0])[i] = 0.f;
        (&g_h2[0][0][0][0])[i] = 0.f;
    }
    if (i < 2*SEQ*4*8) (&g_bar[0][0][0][0])[i] = 0;
}

// ---------------- embedding ----------------
__global__ void embed_kernel(const int* __restrict__ words, const float* __restrict__ emb) {
    int row = blockIdx.x * 8 + (threadIdx.x >> 5);
    int lane = threadIdx.x & 31;
    int w = words[row];
    const float4* src = (const float4*)(emb + (size_t)w * EMB);
    float4*       dst = (float4*)(g_x + (size_t)row * EMB);
    dst[lane] = src[lane];
}

// ---------------- tf32 tensor-core dual GEMM (unchanged from R6) ----------------
__global__ __launch_bounds__(256) void gemm_tf32_dual(
    const float* __restrict__ A,
    const float* __restrict__ Bw_f, const float* __restrict__ Bw_b,
    const float* __restrict__ b1f, const float* __restrict__ b2f,
    const float* __restrict__ b1b, const float* __restrict__ b2b,
    float* __restrict__ Cf, float* __restrict__ Cb,
    int M, int N, int K)
{
    const float* Bw    = blockIdx.z ? Bw_b : Bw_f;
    const float* bias1 = blockIdx.z ? b1b  : b1f;
    const float* bias2 = blockIdx.z ? b2b  : b2f;
    float*       C     = blockIdx.z ? Cb   : Cf;

    __shared__ uint32_t As[2][128][20];
    __shared__ uint32_t Bs[2][128][20];

    const int tid  = threadIdx.x;
    const int lane = tid & 31;
    const int warp = tid >> 5;
    const int m0 = blockIdx.y * 128;
    const int n0 = blockIdx.x * 128;
    const int wm = (warp >> 2) * 64;
    const int wn = (warp & 3) * 32;
    const int ar = lane >> 2;
    const int ac = lane & 3;

    const int lr = tid >> 2;
    const int lk = (tid & 3) * 4;
    const float* Aptr0 = A  + (size_t)(m0 + lr)      * K + lk;
    const float* Aptr1 = A  + (size_t)(m0 + 64 + lr) * K + lk;
    const float* Bptr0 = Bw + (size_t)(n0 + lr)      * K + lk;
    const float* Bptr1 = Bw + (size_t)(n0 + 64 + lr) * K + lk;

    float c[4][4][4];
    #pragma unroll
    for (int i = 0; i < 4; i++)
        #pragma unroll
        for (int j = 0; j < 4; j++)
            #pragma unroll
            for (int r = 0; r < 4; r++) c[i][j][r] = 0.f;

    {
        float4 a0 = *(const float4*)Aptr0;
        float4 a1 = *(const float4*)Aptr1;
        float4 b0 = *(const float4*)Bptr0;
        float4 b1 = *(const float4*)Bptr1;
        As[0][lr][lk+0]=f2tf32(a0.x); As[0][lr][lk+1]=f2tf32(a0.y); As[0][lr][lk+2]=f2tf32(a0.z); As[0][lr][lk+3]=f2tf32(a0.w);
        As[0][64+lr][lk+0]=f2tf32(a1.x); As[0][64+lr][lk+1]=f2tf32(a1.y); As[0][64+lr][lk+2]=f2tf32(a1.z); As[0][64+lr][lk+3]=f2tf32(a1.w);
        Bs[0][lr][lk+0]=f2tf32(b0.x); Bs[0][lr][lk+1]=f2tf32(b0.y); Bs[0][lr][lk+2]=f2tf32(b0.z); Bs[0][lr][lk+3]=f2tf32(b0.w);
        Bs[0][64+lr][lk+0]=f2tf32(b1.x); Bs[0][64+lr][lk+1]=f2tf32(b1.y); Bs[0][64+lr][lk+2]=f2tf32(b1.z); Bs[0][64+lr][lk+3]=f2tf32(b1.w);
    }
    __syncthreads();

    const int T = K / 16;
    float4 pa0, pa1, pb0, pb1;
    for (int tI = 0; tI < T; tI++) {
        const int buf = tI & 1;
        const bool more = (tI + 1 < T);
        if (more) {
            const int off = (tI + 1) * 16;
            pa0 = *(const float4*)(Aptr0 + off);
            pa1 = *(const float4*)(Aptr1 + off);
            pb0 = *(const float4*)(Bptr0 + off);
            pb1 = *(const float4*)(Bptr1 + off);
        }

        #pragma unroll
        for (int kb = 0; kb < 16; kb += 8) {
            uint32_t afr[4][4];
            #pragma unroll
            for (int i = 0; i < 4; i++) {
                int mrow = wm + i*16 + ar;
                afr[i][0] = As[buf][mrow    ][kb + ac];
                afr[i][1] = As[buf][mrow + 8][kb + ac];
                afr[i][2] = As[buf][mrow    ][kb + ac + 4];
                afr[i][3] = As[buf][mrow + 8][kb + ac + 4];
            }
            uint32_t bfr[4][2];
            #pragma unroll
            for (int j = 0; j < 4; j++) {
                int nrow = wn + j*8 + ar;
                bfr[j][0] = Bs[buf][nrow][kb + ac];
                bfr[j][1] = Bs[buf][nrow][kb + ac + 4];
            }
            #pragma unroll
            for (int i = 0; i < 4; i++)
                #pragma unroll
                for (int j = 0; j < 4; j++)
                    mma_tf32(c[i][j][0], c[i][j][1], c[i][j][2], c[i][j][3],
                             afr[i][0], afr[i][1], afr[i][2], afr[i][3],
                             bfr[j][0], bfr[j][1]);
        }

        if (more) {
            const int nb = buf ^ 1;
            __syncthreads();
            As[nb][lr][lk+0]=f2tf32(pa0.x); As[nb][lr][lk+1]=f2tf32(pa0.y); As[nb][lr][lk+2]=f2tf32(pa0.z); As[nb][lr][lk+3]=f2tf32(pa0.w);
            As[nb][64+lr][lk+0]=f2tf32(pa1.x); As[nb][64+lr][lk+1]=f2tf32(pa1.y); As[nb][64+lr][lk+2]=f2tf32(pa1.z); As[nb][64+lr][lk+3]=f2tf32(pa1.w);
            Bs[nb][lr][lk+0]=f2tf32(pb0.x); Bs[nb][lr][lk+1]=f2tf32(pb0.y); Bs[nb][lr][lk+2]=f2tf32(pb0.z); Bs[nb][lr][lk+3]=f2tf32(pb0.w);
            Bs[nb][64+lr][lk+0]=f2tf32(pb1.x); Bs[nb][64+lr][lk+1]=f2tf32(pb1.y); Bs[nb][64+lr][lk+2]=f2tf32(pb1.z); Bs[nb][64+lr][lk+3]=f2tf32(pb1.w);
            __syncthreads();
        }
    }

    #pragma unroll
    for (int i = 0; i < 4; i++) {
        int row0 = m0 + wm + i*16 + ar;
        #pragma unroll
        for (int j = 0; j < 4; j++) {
            int col = n0 + wn + j*8 + 2*ac;
            float bsum0 = bias1[col]   + (bias2 ? bias2[col]   : 0.f);
            float bsum1 = bias1[col+1] + (bias2 ? bias2[col+1] : 0.f);
            *(float2*)(C + (size_t)row0 * N + col)       = make_float2(c[i][j][0] + bsum0, c[i][j][1] + bsum1);
            *(float2*)(C + (size_t)(row0 + 8) * N + col) = make_float2(c[i][j][2] + bsum0, c[i][j][3] + bsum1);
        }
    }
}

// ---------------- fp32 SIMT classifier GEMM (unchanged) ----------------
__global__ __launch_bounds__(256) void sgemm_cls_kernel(
    const float* __restrict__ A, const float* __restrict__ Bw,
    const float* __restrict__ bias1,
    float* __restrict__ C, int M, int N, int K)
{
    const int BM = 128, BN = 128, BK = 16;
    __shared__ float As[2][BK][BM];
    __shared__ float Bs[2][BK][BN];

    const int tid = threadIdx.x;
    const int m0 = blockIdx.y * BM;
    const int n0 = blockIdx.x * BN;
    const int ty = tid >> 4;
    const int tx = tid & 15;

    const int lr = tid >> 2;
    const int lk = (tid & 3) * 4;
    const float* Aptr0 = A + (size_t)(m0 + lr)      * K + lk;
    const float* Aptr1 = A + (size_t)(m0 + 64 + lr) * K + lk;
    const int bn0 = n0 + lr, bn1 = n0 + 64 + lr;
    const float* Bptr0 = Bw + (size_t)bn0 * K + lk;
    const float* Bptr1 = Bw + (size_t)bn1 * K + lk;
    const bool b0ok = bn0 < N, b1ok = bn1 < N;

    float acc[8][8];
    #pragma unroll
    for (int i = 0; i < 8; i++)
        #pragma unroll
        for (int j = 0; j < 8; j++) acc[i][j] = 0.f;

    const float4 z4 = make_float4(0.f,0.f,0.f,0.f);
    float4 av0, av1, bv0, bv1;

    av0 = *(const float4*)Aptr0;
    av1 = *(const float4*)Aptr1;
    bv0 = b0ok ? *(const float4*)Bptr0 : z4;
    bv1 = b1ok ? *(const float4*)Bptr1 : z4;
    As[0][lk+0][lr] = av0.x; As[0][lk+1][lr] = av0.y; As[0][lk+2][lr] = av0.z; As[0][lk+3][lr] = av0.w;
    As[0][lk+0][64+lr] = av1.x; As[0][lk+1][64+lr] = av1.y; As[0][lk+2][64+lr] = av1.z; As[0][lk+3][64+lr] = av1.w;
    Bs[0][lk+0][lr] = bv0.x; Bs[0][lk+1][lr] = bv0.y; Bs[0][lk+2][lr] = bv0.z; Bs[0][lk+3][lr] = bv0.w;
    Bs[0][lk+0][64+lr] = bv1.x; Bs[0][lk+1][64+lr] = bv1.y; Bs[0][lk+2][64+lr] = bv1.z; Bs[0][lk+3][64+lr] = bv1.w;
    __syncthreads();

    const int T = K / BK;
    for (int tI = 0; tI < T; tI++) {
        const int buf = tI & 1;
        const bool more = (tI + 1 < T);
        if (more) {
            const int off = (tI + 1) * BK;
            av0 = *(const float4*)(Aptr0 + off);
            av1 = *(const float4*)(Aptr1 + off);
            bv0 = b0ok ? *(const float4*)(Bptr0 + off) : z4;
            bv1 = b1ok ? *(const float4*)(Bptr1 + off) : z4;
        }
        #pragma unroll
        for (int k = 0; k < BK; k++) {
            float4 a0 = *(const float4*)&As[buf][k][ty*8];
            float4 a1 = *(const float4*)&As[buf][k][ty*8+4];
            float4 b0 = *(const float4*)&Bs[buf][k][tx*8];
            float4 b1 = *(const float4*)&Bs[buf][k][tx*8+4];
            float ar[8] = {a0.x,a0.y,a0.z,a0.w,a1.x,a1.y,a1.z,a1.w};
            float br[8] = {b0.x,b0.y,b0.z,b0.w,b1.x,b1.y,b1.z,b1.w};
            #pragma unroll
            for (int i = 0; i < 8; i++)
                #pragma unroll
                for (int j = 0; j < 8; j++)
                    acc[i][j] = fmaf(ar[i], br[j], acc[i][j]);
        }
        if (more) {
            const int nb = buf ^ 1;
            __syncthreads();
            As[nb][lk+0][lr] = av0.x; As[nb][lk+1][lr] = av0.y; As[nb][lk+2][lr] = av0.z; As[nb][lk+3][lr] = av0.w;
            As[nb][lk+0][64+lr] = av1.x; As[nb][lk+1][64+lr] = av1.y; As[nb][lk+2][64+lr] = av1.z; As[nb][lk+3][64+lr] = av1.w;
            Bs[nb][lk+0][lr] = bv0.x; Bs[nb][lk+1][lr] = bv0.y; Bs[nb][lk+2][lr] = bv0.z; Bs[nb][lk+3][lr] = bv0.w;
            Bs[nb][lk+0][64+lr] = bv1.x; Bs[nb][lk+1][64+lr] = bv1.y; Bs[nb][lk+2][64+lr] = bv1.z; Bs[nb][lk+3][64+lr] = bv1.w;
            __syncthreads();
        }
    }

    #pragma unroll
    for (int i = 0; i < 8; i++) {
        int m = m0 + ty*8 + i;
        #pragma unroll
        for (int j = 0; j < 8; j++) {
            int n = n0 + tx*8 + j;
            if (n < N) C[(size_t)m * N + n] = acc[i][j] + bias1[n];
        }
    }
}

// ---------------- persistent BiLSTM recurrence: tf32 mma, W resident in registers ----------
// 128 blocks = dir(2) x jslice(32, 8 j each) x bhalf(2, 32 b each); 256 threads (8 warps).
// Warp w: mw=w&1 (16-row m-tile), nw2=(w>>1)&1 (16-batch group, 2 n-atoms), kh=w>>2 (128-k half).
// Whh slice lives in 64 regs/warp of tf32 A-fragments for all 512 steps.
// h staged per step into hi/lo tf32 smem arrays (stride 40 -> conflict-free B frags).
// SMEM floats: ht_hi 256*40=10240, ht_lo 10240, part 2*32*33=2112, xg 32*33=1056,
//              hst 256, lens 32  -> 23936 floats = 95744 B
#define SMEM_RECUR (23936 * 4)

__global__ __launch_bounds__(256, 1) void recur_kernel(
    const float* __restrict__ xg_f, const float* __restrict__ xg_b,
    const float* __restrict__ Whh_f, const float* __restrict__ Whh_b,
    const int* __restrict__ lengths, float* __restrict__ out,
    float* __restrict__ hbuf, int* __restrict__ bar)
{
    extern __shared__ float smem[];
    float* ht_hi  = smem;                    // [256 k][40]
    float* ht_lo  = smem + 10240;            // [256 k][40]
    float* part   = smem + 20480;            // [2 kh][32 r][33]
    float* xg_sm  = smem + 22592;            // [32 b][33]
    float* hst    = smem + 23648;            // [8 jj][32 b]
    int*   lens_sm= (int*)(smem + 23904);    // [32]

    const int tid  = threadIdx.x;
    const int lane = tid & 31;
    const int warp = tid >> 5;
    const int blk = blockIdx.x;
    const int dir    = blk >> 6;
    const int jslice = (blk >> 1) & 31;
    const int bh     = blk & 1;
    const int j0 = jslice * 8;
    const int b0 = bh * 32;
    const int grp = dir * 2 + bh;
    const float* Whh = dir ? Whh_b : Whh_f;
    const float* xg  = dir ? xg_b  : xg_f;

    // warp mma coordinates
    const int mw  = warp & 1;            // m-tile (rows 16*mw .. +15)
    const int nw2 = (warp >> 1) & 1;     // batch group (16*nw2 .. +15)
    const int kh  = warp >> 2;           // k half (128*kh .. +127)
    const int lg  = lane >> 2;           // 0..7
    const int lc  = lane & 3;            // 0..3
    const int bcol0 = 16*nw2 + lg;       // n-atom 0 batch col
    const int khbase = kh * 128;

    // one-time Whh A-fragment load (resident for all 512 steps)
    uint32_t wfrag[16][4];
    #pragma unroll
    for (int ka = 0; ka < 16; ka++) {
        #pragma unroll
        for (int i = 0; i < 4; i++) {
            int r   = 16*mw + lg + (i & 1) * 8;          // local row 0..31
            int col = khbase + ka*8 + lc + (i >> 1) * 4; // k
            int g = r >> 3, jj = r & 7;
            wfrag[ka][i] = f2tf32(Whh[(size_t)(g*HID + j0 + jj) * HID + col]);
        }
    }
    if (tid < 32) lens_sm[tid] = lengths[b0 + tid];

    // xg staging mapping (thread -> one float4/step)
    const int sb    = tid >> 3;          // 0..31 batch
    const int sg    = (tid >> 1) & 3;    // gate
    const int shalf = tid & 1;
    const size_t xg_row_base = ((size_t)(b0 + sb) * SEQ);
    const int xg_col = sg*HID + j0 + shalf*4;

    // combine mapping
    const int rr = tid >> 5;             // jj 0..7
    const int cb = tid & 31;             // batch 0..31
    float c_reg = 0.f;

    __syncthreads();

    int t0 = dir ? (SEQ - 1) : 0;
    float4 xg_pf = __ldg((const float4*)(xg + (xg_row_base + t0) * G4 + xg_col));

    for (int s = 0; s < SEQ; s++) {
        const int t = dir ? (SEQ - 1 - s) : s;

        if (s > 0) {
            if (tid == 0) {
                int* cnt = bar + ((s-1)*4 + grp)*8;
                while (ld_acquire(cnt) < GRP_BLOCKS) __nanosleep(32);
            }
            __syncthreads();
        }

        // stage xg + h (hi/lo tf32 split) + prefetch next xg
        {
            float* xd = xg_sm + sb*33 + sg*8 + shalf*4;
            xd[0] = xg_pf.x; xd[1] = xg_pf.y; xd[2] = xg_pf.z; xd[3] = xg_pf.w;

            const float* hsrc = hbuf + (size_t)((s & 1)*2 + dir) * HID * BATCH;
            #pragma unroll
            for (int n = 0; n < 8; n++) {
                int i = tid + n*256;                 // 0..2047
                int k = i >> 3, o = (i & 7)*4;
                float4 v = __ldcg((const float4*)(hsrc + k*BATCH + b0 + o));
                float hx[4] = {v.x, v.y, v.z, v.w};
                float4 hi4, lo4;
                float* hip = (float*)&hi4;
                float* lop = (float*)&lo4;
                #pragma unroll
                for (int e = 0; e < 4; e++) {
                    float hv = __uint_as_float(f2tf32(hx[e]));
                    hip[e] = hv;
                    lop[e] = __uint_as_float(f2tf32(hx[e] - hv));
                }
                *(float4*)(ht_hi + k*HSTRIDE + o) = hi4;
                *(float4*)(ht_lo + k*HSTRIDE + o) = lo4;
            }

            if (s + 1 < SEQ) {
                int tn = dir ? (SEQ - 2 - s) : (s + 1);
                xg_pf = __ldg((const float4*)(xg + (xg_row_base + tn) * G4 + xg_col));
            }
        }
        __syncthreads();

        // tensor-core gate GEMM over this warp's k-half
        {
            float acc[2][4];
            #pragma unroll
            for (int na = 0; na < 2; na++)
                #pragma unroll
                for (int r = 0; r < 4; r++) acc[na][r] = 0.f;

            #pragma unroll
            for (int ka = 0; ka < 16; ka++) {
                const int krow = khbase + ka*8 + lc;
                const float* hi_p = ht_hi + krow*HSTRIDE;
                const float* lo_p = ht_lo + krow*HSTRIDE;
                #pragma unroll
                for (int na = 0; na < 2; na++) {
                    const int bc = bcol0 + na*8;
                    uint32_t bh0 = __float_as_uint(hi_p[bc]);
                    uint32_t bh1 = __float_as_uint(hi_p[4*HSTRIDE + bc]);
                    uint32_t bl0 = __float_as_uint(lo_p[bc]);
                    uint32_t bl1 = __float_as_uint(lo_p[4*HSTRIDE + bc]);
                    mma_tf32(acc[na][0], acc[na][1], acc[na][2], acc[na][3],
                             wfrag[ka][0], wfrag[ka][1], wfrag[ka][2], wfrag[ka][3],
                             bh0, bh1);
                    mma_tf32(acc[na][0], acc[na][1], acc[na][2], acc[na][3],
                             wfrag[ka][0], wfrag[ka][1], wfrag[ka][2], wfrag[ka][3],
                             bl0, bl1);
                }
            }

            // write partials: part[kh][r][b]
            float* pd = part + kh*1056;
            #pragma unroll
            for (int na = 0; na < 2; na++) {
                int col = 16*nw2 + na*8 + 2*lc;
                int row = 16*mw + lg;
                pd[row*33 + col]         = acc[na][0];
                pd[row*33 + col + 1]     = acc[na][1];
                pd[(row + 8)*33 + col]   = acc[na][2];
                pd[(row + 8)*33 + col+1] = acc[na][3];
            }
        }
        __syncthreads();

        // combine: thread = (jj=rr, b=cb)
        {
            float gate[4];
            #pragma unroll
            for (int g = 0; g < 4; g++) {
                int r = g*8 + rr;
                gate[g] = part[r*33 + cb] + part[1056 + r*33 + cb]
                        + xg_sm[cb*33 + g*8 + rr];
            }
            float c_new = sigf(gate[1]) * c_reg + sigf(gate[0]) * tanhf_(gate[2]);
            float h_new = sigf(gate[3]) * tanhf_(c_new);
            float h_prev = ht_hi[(j0 + rr)*HSTRIDE + cb] + ht_lo[(j0 + rr)*HSTRIDE + cb];
            bool  m = (t < lens_sm[cb]);
            float h_out = m ? h_new : h_prev;
            c_reg       = m ? c_new : c_reg;

            hbuf[(size_t)(((s+1) & 1)*2 + dir) * HID * BATCH + (j0 + rr)*BATCH + b0 + cb] = h_out;
            hst[rr*32 + cb] = h_out;
        }
        __syncthreads();
        if (tid == 0) red_release_add(bar + (s*4 + grp)*8, 1);

        // semi-coalesced out store (64 threads x float4)
        if (tid < 64) {
            int bb  = tid >> 1;
            int seg = tid & 1;
            float4 v;
            v.x = hst[(seg*4+0)*32 + bb];
            v.y = hst[(seg*4+1)*32 + bb];
            v.z = hst[(seg*4+2)*32 + bb];
            v.w = hst[(seg*4+3)*32 + bb];
            *(float4*)(out + ((size_t)(b0 + bb) * SEQ + t) * (2*HID) + dir*HID + j0 + seg*4) = v;
        }
    }
}

// ---------------- launch ----------------
extern "C" void kernel_launch(void* const* d_in, const int* in_sizes, int n_in,
                              void* d_out, int out_size)
{
    (void)in_sizes; (void)n_in; (void)out_size;
    const int*   words    = (const int*)  d_in[0];
    const int*   lengths  = (const int*)  d_in[1];
    const float* emb      = (const float*)d_in[2];
    const float* l1f_Wih  = (const float*)d_in[3];
    const float* l1f_Whh  = (const float*)d_in[4];
    const float* l1f_bih  = (const float*)d_in[5];
    const float* l1f_bhh  = (const float*)d_in[6];
    const float* l1b_Wih  = (const float*)d_in[7];
    const float* l1b_Whh  = (const float*)d_in[8];
    const float* l1b_bih  = (const float*)d_in[9];
    const float* l1b_bhh  = (const float*)d_in[10];
    const float* l2f_Wih  = (const float*)d_in[11];
    const float* l2f_Whh  = (const float*)d_in[12];
    const float* l2f_bih  = (const float*)d_in[13];
    const float* l2f_bhh  = (const float*)d_in[14];
    const float* l2b_Wih  = (const float*)d_in[15];
    const float* l2b_Whh  = (const float*)d_in[16];
    const float* l2b_bih  = (const float*)d_in[17];
    const float* l2b_bhh  = (const float*)d_in[18];
    const float* cls_W    = (const float*)d_in[19];
    const float* cls_b    = (const float*)d_in[20];
    float* out = (float*)d_out;

    float *px, *pxf, *pxb, *po1, *po2, *ph1, *ph2;
    int *pbar;
    cudaGetSymbolAddress((void**)&px,   g_x);
    cudaGetSymbolAddress((void**)&pxf,  g_xg_f);
    cudaGetSymbolAddress((void**)&pxb,  g_xg_b);
    cudaGetSymbolAddress((void**)&po1,  g_o1);
    cudaGetSymbolAddress((void**)&po2,  g_o2);
    cudaGetSymbolAddress((void**)&ph1,  g_h1);
    cudaGetSymbolAddress((void**)&ph2,  g_h2);
    cudaGetSymbolAddress((void**)&pbar, g_bar);

    cudaFuncSetAttribute(recur_kernel, cudaFuncAttributeMaxDynamicSharedMemorySize, SMEM_RECUR);

    // 1) init
    init_kernel<<<256, 256>>>();

    // 2) embedding
    embed_kernel<<<M_ROWS/8, 256>>>(words, emb);

    // 3) layer-1 input projections
    dim3 gx(G4/128, M_ROWS/128, 2);
    gemm_tf32_dual<<<gx, 256>>>(px, l1f_Wih, l1b_Wih,
                                l1f_bih, l1f_bhh, l1b_bih, l1b_bhh,
                                pxf, pxb, M_ROWS, G4, EMB);

    // 4) layer-1 recurrence
    recur_kernel<<<REC_BLOCKS, 256, SMEM_RECUR>>>(pxf, pxb, l1f_Whh, l1b_Whh,
                                                  lengths, po1, ph1, pbar);

    // 5) layer-2 input projections
    gemm_tf32_dual<<<gx, 256>>>(po1, l2f_Wih, l2b_Wih,
                                l2f_bih, l2f_bhh, l2b_bih, l2b_bhh,
                                pxf, pxb, M_ROWS, G4, 2*HID);

    // 6) layer-2 recurrence
    recur_kernel<<<REC_BLOCKS, 256, SMEM_RECUR>>>(pxf, pxb, l2f_Whh, l2b_Whh,
                                                  lengths, po2, ph2, pbar + SEQ*4*8);

    // 7) classifier (fp32)
    dim3 gc(1, M_ROWS/128, 1);
    sgemm_cls_kernel<<<gc, 256>>>(po2, cls_W, cls_b, out, M_ROWS, NTAGS, 2*HID);
}

// round 9
// speedup vs baseline: 3.2224x; 1.1559x over previous
#include <cuda_runtime.h>
#include <cstdint>

#define BATCH 64
#define SEQ   512
#define EMB   128
#define HID   256
#define G4    1024            // 4*HID
#define NTAGS 50
#define M_ROWS (BATCH*SEQ)    // 32768
#define REC_BLOCKS 128        // 2 dirs * 32 j-slices * 2 batch-halves
#define GRP_BLOCKS 32         // blocks per (dir, bhalf) barrier group
#define HSTRIDE 40            // smem row stride (floats) for conflict-free B frags

// ---------------- scratch (device globals; allocation-free) ----------------
__device__ float g_x   [(size_t)M_ROWS*EMB];
__device__ float g_xg_f[(size_t)M_ROWS*G4];
__device__ float g_xg_b[(size_t)M_ROWS*G4];
__device__ float g_o1  [(size_t)M_ROWS*2*HID];
__device__ float g_o2  [(size_t)M_ROWS*2*HID];
__device__ float g_h1  [2][2][HID][BATCH];        // [parity][dir][k][b]
__device__ float g_h2  [2][2][HID][BATCH];
__device__ int   g_bar [2][SEQ][4][8];            // [layer][step][group][pad]

// ---------------- helpers ----------------
__device__ __forceinline__ int ld_acquire(const int* p) {
    int v;
    asm volatile("ld.global.acquire.gpu.b32 %0, [%1];" : "=r"(v) : "l"(p));
    return v;
}
__device__ __forceinline__ void red_release_add(int* p, int v) {
    asm volatile("red.release.gpu.global.add.u32 [%0], %1;" :: "l"(p), "r"(v) : "memory");
}
__device__ __forceinline__ float sigf(float x)  { return 1.f/(1.f + __expf(-x)); }
__device__ __forceinline__ float tanhf_(float x){ return 1.f - 2.f/(__expf(2.f*x) + 1.f); }
__device__ __forceinline__ uint32_t f2tf32(float f) {
    uint32_t u;
    asm("cvt.rna.tf32.f32 %0, %1;" : "=r"(u) : "f"(f));
    return u;
}
__device__ __forceinline__ void mma_tf32(float& c0, float& c1, float& c2, float& c3,
                                         uint32_t a0, uint32_t a1, uint32_t a2, uint32_t a3,
                                         uint32_t b0, uint32_t b1) {
    asm volatile("mma.sync.aligned.m16n8k8.row.col.f32.tf32.tf32.f32 "
                 "{%0,%1,%2,%3}, {%4,%5,%6,%7}, {%8,%9}, {%0,%1,%2,%3};"
                 : "+f"(c0), "+f"(c1), "+f"(c2), "+f"(c3)
                 : "r"(a0), "r"(a1), "r"(a2), "r"(a3), "r"(b0), "r"(b1));
}

// ---------------- init ----------------
__global__ void init_kernel() {
    int i = blockIdx.x * blockDim.x + threadIdx.x;
    if (i < 2*2*HID*BATCH) {
        (&g_h1[0][0][0][0])[i] = 0.f;
        (&g_h2[0][0][0][0])[i] = 0.f;
    }
    if (i < 2*SEQ*4*8) (&g_bar[0][0][0][0])[i] = 0;
}

// ---------------- embedding ----------------
__global__ void embed_kernel(const int* __restrict__ words, const float* __restrict__ emb) {
    int row = blockIdx.x * 8 + (threadIdx.x >> 5);
    int lane = threadIdx.x & 31;
    int w = words[row];
    const float4* src = (const float4*)(emb + (size_t)w * EMB);
    float4*       dst = (float4*)(g_x + (size_t)row * EMB);
    dst[lane] = src[lane];
}

// ---------------- tf32 tensor-core dual GEMM ----------------
__global__ __launch_bounds__(256) void gemm_tf32_dual(
    const float* __restrict__ A,
    const float* __restrict__ Bw_f, const float* __restrict__ Bw_b,
    const float* __restrict__ b1f, const float* __restrict__ b2f,
    const float* __restrict__ b1b, const float* __restrict__ b2b,
    float* __restrict__ Cf, float* __restrict__ Cb,
    int M, int N, int K)
{
    const float* Bw    = blockIdx.z ? Bw_b : Bw_f;
    const float* bias1 = blockIdx.z ? b1b  : b1f;
    const float* bias2 = blockIdx.z ? b2b  : b2f;
    float*       C     = blockIdx.z ? Cb   : Cf;

    __shared__ uint32_t As[2][128][20];
    __shared__ uint32_t Bs[2][128][20];

    const int tid  = threadIdx.x;
    const int lane = tid & 31;
    const int warp = tid >> 5;
    const int m0 = blockIdx.y * 128;
    const int n0 = blockIdx.x * 128;
    const int wm = (warp >> 2) * 64;
    const int wn = (warp & 3) * 32;
    const int ar = lane >> 2;
    const int ac = lane & 3;

    const int lr = tid >> 2;
    const int lk = (tid & 3) * 4;
    const float* Aptr0 = A  + (size_t)(m0 + lr)      * K + lk;
    const float* Aptr1 = A  + (size_t)(m0 + 64 + lr) * K + lk;
    const float* Bptr0 = Bw + (size_t)(n0 + lr)      * K + lk;
    const float* Bptr1 = Bw + (size_t)(n0 + 64 + lr) * K + lk;

    float c[4][4][4];
    #pragma unroll
    for (int i = 0; i < 4; i++)
        #pragma unroll
        for (int j = 0; j < 4; j++)
            #pragma unroll
            for (int r = 0; r < 4; r++) c[i][j][r] = 0.f;

    {
        float4 a0 = *(const float4*)Aptr0;
        float4 a1 = *(const float4*)Aptr1;
        float4 b0 = *(const float4*)Bptr0;
        float4 b1 = *(const float4*)Bptr1;
        As[0][lr][lk+0]=f2tf32(a0.x); As[0][lr][lk+1]=f2tf32(a0.y); As[0][lr][lk+2]=f2tf32(a0.z); As[0][lr][lk+3]=f2tf32(a0.w);
        As[0][64+lr][lk+0]=f2tf32(a1.x); As[0][64+lr][lk+1]=f2tf32(a1.y); As[0][64+lr][lk+2]=f2tf32(a1.z); As[0][64+lr][lk+3]=f2tf32(a1.w);
        Bs[0][lr][lk+0]=f2tf32(b0.x); Bs[0][lr][lk+1]=f2tf32(b0.y); Bs[0][lr][lk+2]=f2tf32(b0.z); Bs[0][lr][lk+3]=f2tf32(b0.w);
        Bs[0][64+lr][lk+0]=f2tf32(b1.x); Bs[0][64+lr][lk+1]=f2tf32(b1.y); Bs[0][64+lr][lk+2]=f2tf32(b1.z); Bs[0][64+lr][lk+3]=f2tf32(b1.w);
    }
    __syncthreads();

    const int T = K / 16;
    float4 pa0, pa1, pb0, pb1;
    for (int tI = 0; tI < T; tI++) {
        const int buf = tI & 1;
        const bool more = (tI + 1 < T);
        if (more) {
            const int off = (tI + 1) * 16;
            pa0 = *(const float4*)(Aptr0 + off);
            pa1 = *(const float4*)(Aptr1 + off);
            pb0 = *(const float4*)(Bptr0 + off);
            pb1 = *(const float4*)(Bptr1 + off);
        }

        #pragma unroll
        for (int kb = 0; kb < 16; kb += 8) {
            uint32_t afr[4][4];
            #pragma unroll
            for (int i = 0; i < 4; i++) {
                int mrow = wm + i*16 + ar;
                afr[i][0] = As[buf][mrow    ][kb + ac];
                afr[i][1] = As[buf][mrow + 8][kb + ac];
                afr[i][2] = As[buf][mrow    ][kb + ac + 4];
                afr[i][3] = As[buf][mrow + 8][kb + ac + 4];
            }
            uint32_t bfr[4][2];
            #pragma unroll
            for (int j = 0; j < 4; j++) {
                int nrow = wn + j*8 + ar;
                bfr[j][0] = Bs[buf][nrow][kb + ac];
                bfr[j][1] = Bs[buf][nrow][kb + ac + 4];
            }
            #pragma unroll
            for (int i = 0; i < 4; i++)
                #pragma unroll
                for (int j = 0; j < 4; j++)
                    mma_tf32(c[i][j][0], c[i][j][1], c[i][j][2], c[i][j][3],
                             afr[i][0], afr[i][1], afr[i][2], afr[i][3],
                             bfr[j][0], bfr[j][1]);
        }

        if (more) {
            const int nb = buf ^ 1;
            __syncthreads();
            As[nb][lr][lk+0]=f2tf32(pa0.x); As[nb][lr][lk+1]=f2tf32(pa0.y); As[nb][lr][lk+2]=f2tf32(pa0.z); As[nb][lr][lk+3]=f2tf32(pa0.w);
            As[nb][64+lr][lk+0]=f2tf32(pa1.x); As[nb][64+lr][lk+1]=f2tf32(pa1.y); As[nb][64+lr][lk+2]=f2tf32(pa1.z); As[nb][64+lr][lk+3]=f2tf32(pa1.w);
            Bs[nb][lr][lk+0]=f2tf32(pb0.x); Bs[nb][lr][lk+1]=f2tf32(pb0.y); Bs[nb][lr][lk+2]=f2tf32(pb0.z); Bs[nb][lr][lk+3]=f2tf32(pb0.w);
            Bs[nb][64+lr][lk+0]=f2tf32(pb1.x); Bs[nb][64+lr][lk+1]=f2tf32(pb1.y); Bs[nb][64+lr][lk+2]=f2tf32(pb1.z); Bs[nb][64+lr][lk+3]=f2tf32(pb1.w);
            __syncthreads();
        }
    }

    #pragma unroll
    for (int i = 0; i < 4; i++) {
        int row0 = m0 + wm + i*16 + ar;
        #pragma unroll
        for (int j = 0; j < 4; j++) {
            int col = n0 + wn + j*8 + 2*ac;
            float bsum0 = bias1[col]   + (bias2 ? bias2[col]   : 0.f);
            float bsum1 = bias1[col+1] + (bias2 ? bias2[col+1] : 0.f);
            *(float2*)(C + (size_t)row0 * N + col)       = make_float2(c[i][j][0] + bsum0, c[i][j][1] + bsum1);
            *(float2*)(C + (size_t)(row0 + 8) * N + col) = make_float2(c[i][j][2] + bsum0, c[i][j][3] + bsum1);
        }
    }
}

// ---------------- fp32 SIMT classifier GEMM ----------------
__global__ __launch_bounds__(256) void sgemm_cls_kernel(
    const float* __restrict__ A, const float* __restrict__ Bw,
    const float* __restrict__ bias1,
    float* __restrict__ C, int M, int N, int K)
{
    const int BM = 128, BN = 128, BK = 16;
    __shared__ float As[2][BK][BM];
    __shared__ float Bs[2][BK][BN];

    const int tid = threadIdx.x;
    const int m0 = blockIdx.y * BM;
    const int n0 = blockIdx.x * BN;
    const int ty = tid >> 4;
    const int tx = tid & 15;

    const int lr = tid >> 2;
    const int lk = (tid & 3) * 4;
    const float* Aptr0 = A + (size_t)(m0 + lr)      * K + lk;
    const float* Aptr1 = A + (size_t)(m0 + 64 + lr) * K + lk;
    const int bn0 = n0 + lr, bn1 = n0 + 64 + lr;
    const float* Bptr0 = Bw + (size_t)bn0 * K + lk;
    const float* Bptr1 = Bw + (size_t)bn1 * K + lk;
    const bool b0ok = bn0 < N, b1ok = bn1 < N;

    float acc[8][8];
    #pragma unroll
    for (int i = 0; i < 8; i++)
        #pragma unroll
        for (int j = 0; j < 8; j++) acc[i][j] = 0.f;

    const float4 z4 = make_float4(0.f,0.f,0.f,0.f);
    float4 av0, av1, bv0, bv1;

    av0 = *(const float4*)Aptr0;
    av1 = *(const float4*)Aptr1;
    bv0 = b0ok ? *(const float4*)Bptr0 : z4;
    bv1 = b1ok ? *(const float4*)Bptr1 : z4;
    As[0][lk+0][lr] = av0.x; As[0][lk+1][lr] = av0.y; As[0][lk+2][lr] = av0.z; As[0][lk+3][lr] = av0.w;
    As[0][lk+0][64+lr] = av1.x; As[0][lk+1][64+lr] = av1.y; As[0][lk+2][64+lr] = av1.z; As[0][lk+3][64+lr] = av1.w;
    Bs[0][lk+0][lr] = bv0.x; Bs[0][lk+1][lr] = bv0.y; Bs[0][lk+2][lr] = bv0.z; Bs[0][lk+3][lr] = bv0.w;
    Bs[0][lk+0][64+lr] = bv1.x; Bs[0][lk+1][64+lr] = bv1.y; Bs[0][lk+2][64+lr] = bv1.z; Bs[0][lk+3][64+lr] = bv1.w;
    __syncthreads();

    const int T = K / BK;
    for (int tI = 0; tI < T; tI++) {
        const int buf = tI & 1;
        const bool more = (tI + 1 < T);
        if (more) {
            const int off = (tI + 1) * BK;
            av0 = *(const float4*)(Aptr0 + off);
            av1 = *(const float4*)(Aptr1 + off);
            bv0 = b0ok ? *(const float4*)(Bptr0 + off) : z4;
            bv1 = b1ok ? *(const float4*)(Bptr1 + off) : z4;
        }
        #pragma unroll
        for (int k = 0; k < BK; k++) {
            float4 a0 = *(const float4*)&As[buf][k][ty*8];
            float4 a1 = *(const float4*)&As[buf][k][ty*8+4];
            float4 b0 = *(const float4*)&Bs[buf][k][tx*8];
            float4 b1 = *(const float4*)&Bs[buf][k][tx*8+4];
            float ar[8] = {a0.x,a0.y,a0.z,a0.w,a1.x,a1.y,a1.z,a1.w};
            float br[8] = {b0.x,b0.y,b0.z,b0.w,b1.x,b1.y,b1.z,b1.w};
            #pragma unroll
            for (int i = 0; i < 8; i++)
                #pragma unroll
                for (int j = 0; j < 8; j++)
                    acc[i][j] = fmaf(ar[i], br[j], acc[i][j]);
        }
        if (more) {
            const int nb = buf ^ 1;
            __syncthreads();
            As[nb][lk+0][lr] = av0.x; As[nb][lk+1][lr] = av0.y; As[nb][lk+2][lr] = av0.z; As[nb][lk+3][lr] = av0.w;
            As[nb][lk+0][64+lr] = av1.x; As[nb][lk+1][64+lr] = av1.y; As[nb][lk+2][64+lr] = av1.z; As[nb][lk+3][64+lr] = av1.w;
            Bs[nb][lk+0][lr] = bv0.x; Bs[nb][lk+1][lr] = bv0.y; Bs[nb][lk+2][lr] = bv0.z; Bs[nb][lk+3][lr] = bv0.w;
            Bs[nb][lk+0][64+lr] = bv1.x; Bs[nb][lk+1][64+lr] = bv1.y; Bs[nb][lk+2][64+lr] = bv1.z; Bs[nb][lk+3][64+lr] = bv1.w;
            __syncthreads();
        }
    }

    #pragma unroll
    for (int i = 0; i < 8; i++) {
        int m = m0 + ty*8 + i;
        #pragma unroll
        for (int j = 0; j < 8; j++) {
            int n = n0 + tx*8 + j;
            if (n < N) C[(size_t)m * N + n] = acc[i][j] + bias1[n];
        }
    }
}

// ---------------- persistent BiLSTM recurrence: tf32 mma, single-tf32 h ----------------
// 128 blocks = dir(2) x jslice(32, 8 j each) x bhalf(2, 32 b each); 256 threads (8 warps).
// Warp w: mw=w&1 (16-row m-tile), nw2=(w>>1)&1 (16-batch group), kh=w>>2 (128-k half).
// Whh resident in regs (tf32 A-frags). h staged per step as tf32 (mma input only);
// full-precision masked pass-through uses the block's own previous hst (exact).
// SMEM floats: ht 256*40=10240, part 2*32*33=2112, xg 32*33=1056, hst 256, lens 32 = 13696
#define SMEM_RECUR (13696 * 4)

__global__ __launch_bounds__(256, 1) void recur_kernel(
    const float* __restrict__ xg_f, const float* __restrict__ xg_b,
    const float* __restrict__ Whh_f, const float* __restrict__ Whh_b,
    const int* __restrict__ lengths, float* __restrict__ out,
    float* __restrict__ hbuf, int* __restrict__ bar)
{
    extern __shared__ float smem[];
    float* ht     = smem;                    // [256 k][40] tf32 values
    float* part   = smem + 10240;            // [2 kh][32 r][33]
    float* xg_sm  = smem + 12352;            // [32 b][33]
    float* hst    = smem + 13408;            // [8 jj][32 b]  (this block's fp32 h)
    int*   lens_sm= (int*)(smem + 13664);    // [32]

    const int tid  = threadIdx.x;
    const int lane = tid & 31;
    const int warp = tid >> 5;
    const int blk = blockIdx.x;
    const int dir    = blk >> 6;
    const int jslice = (blk >> 1) & 31;
    const int bh     = blk & 1;
    const int j0 = jslice * 8;
    const int b0 = bh * 32;
    const int grp = dir * 2 + bh;
    const float* Whh = dir ? Whh_b : Whh_f;
    const float* xg  = dir ? xg_b  : xg_f;

    // warp mma coordinates
    const int mw  = warp & 1;
    const int nw2 = (warp >> 1) & 1;
    const int kh  = warp >> 2;
    const int lg  = lane >> 2;
    const int lc  = lane & 3;
    const int bcol0 = 16*nw2 + lg;
    const int khbase = kh * 128;

    // one-time Whh A-fragment load (resident all steps)
    uint32_t wfrag[16][4];
    #pragma unroll
    for (int ka = 0; ka < 16; ka++) {
        #pragma unroll
        for (int i = 0; i < 4; i++) {
            int r   = 16*mw + lg + (i & 1) * 8;
            int col = khbase + ka*8 + lc + (i >> 1) * 4;
            int g = r >> 3, jj = r & 7;
            wfrag[ka][i] = f2tf32(Whh[(size_t)(g*HID + j0 + jj) * HID + col]);
        }
    }
    if (tid < 32) lens_sm[tid] = lengths[b0 + tid];
    hst[tid] = 0.f;                      // h(s=0) = 0 for this block's j-slice

    // xg staging mapping
    const int sb    = tid >> 3;
    const int sg    = (tid >> 1) & 3;
    const int shalf = tid & 1;
    const size_t xg_row_base = ((size_t)(b0 + sb) * SEQ);
    const int xg_col = sg*HID + j0 + shalf*4;

    // combine mapping
    const int rr = tid >> 5;
    const int cb = tid & 31;
    float c_reg = 0.f;

    __syncthreads();

    int t0 = dir ? (SEQ - 1) : 0;
    float4 xg_pf = __ldg((const float4*)(xg + (xg_row_base + t0) * G4 + xg_col));

    for (int s = 0; s < SEQ; s++) {
        const int t = dir ? (SEQ - 1 - s) : s;

        if (s > 0) {
            if (tid == 0) {
                int* cnt = bar + ((s-1)*4 + grp)*8;
                while (ld_acquire(cnt) < GRP_BLOCKS) __nanosleep(40);
            }
            __syncthreads();
        }

        // stage xg + h (tf32) + prefetch next xg
        {
            float* xd = xg_sm + sb*33 + sg*8 + shalf*4;
            xd[0] = xg_pf.x; xd[1] = xg_pf.y; xd[2] = xg_pf.z; xd[3] = xg_pf.w;

            const float* hsrc = hbuf + (size_t)((s & 1)*2 + dir) * HID * BATCH;
            #pragma unroll
            for (int n = 0; n < 8; n++) {
                int i = tid + n*256;                 // 0..2047
                int k = i >> 3, o = (i & 7)*4;
                float4 v = __ldcg((const float4*)(hsrc + k*BATCH + b0 + o));
                float4 tv;
                tv.x = __uint_as_float(f2tf32(v.x));
                tv.y = __uint_as_float(f2tf32(v.y));
                tv.z = __uint_as_float(f2tf32(v.z));
                tv.w = __uint_as_float(f2tf32(v.w));
                *(float4*)(ht + k*HSTRIDE + o) = tv;
            }

            if (s + 1 < SEQ) {
                int tn = dir ? (SEQ - 2 - s) : (s + 1);
                xg_pf = __ldg((const float4*)(xg + (xg_row_base + tn) * G4 + xg_col));
            }
        }
        __syncthreads();

        // tensor-core gate GEMM over this warp's k-half
        {
            float acc[2][4];
            #pragma unroll
            for (int na = 0; na < 2; na++)
                #pragma unroll
                for (int r = 0; r < 4; r++) acc[na][r] = 0.f;

            #pragma unroll
            for (int ka = 0; ka < 16; ka++) {
                const float* hp = ht + (khbase + ka*8 + lc)*HSTRIDE;
                #pragma unroll
                for (int na = 0; na < 2; na++) {
                    const int bc = bcol0 + na*8;
                    uint32_t bf0 = __float_as_uint(hp[bc]);
                    uint32_t bf1 = __float_as_uint(hp[4*HSTRIDE + bc]);
                    mma_tf32(acc[na][0], acc[na][1], acc[na][2], acc[na][3],
                             wfrag[ka][0], wfrag[ka][1], wfrag[ka][2], wfrag[ka][3],
                             bf0, bf1);
                }
            }

            float* pd = part + kh*1056;
            #pragma unroll
            for (int na = 0; na < 2; na++) {
                int col = 16*nw2 + na*8 + 2*lc;
                int row = 16*mw + lg;
                pd[row*33 + col]         = acc[na][0];
                pd[row*33 + col + 1]     = acc[na][1];
                pd[(row + 8)*33 + col]   = acc[na][2];
                pd[(row + 8)*33 + col+1] = acc[na][3];
            }
        }
        __syncthreads();

        // combine: thread = (jj=rr, b=cb); h_prev from our own previous hst (fp32-exact)
        {
            float gate[4];
            #pragma unroll
            for (int g = 0; g < 4; g++) {
                int r = g*8 + rr;
                gate[g] = part[r*33 + cb] + part[1056 + r*33 + cb]
                        + xg_sm[cb*33 + g*8 + rr];
            }
            float h_prev = hst[rr*32 + cb];
            float c_new = sigf(gate[1]) * c_reg + sigf(gate[0]) * tanhf_(gate[2]);
            float h_new = sigf(gate[3]) * tanhf_(c_new);
            bool  m = (t < lens_sm[cb]);
            float h_out = m ? h_new : h_prev;
            c_reg       = m ? c_new : c_reg;

            hbuf[(size_t)(((s+1) & 1)*2 + dir) * HID * BATCH + (j0 + rr)*BATCH + b0 + cb] = h_out;
            hst[rr*32 + cb] = h_out;
        }
        __syncthreads();
        if (tid == 0) red_release_add(bar + (s*4 + grp)*8, 1);

        // semi-coalesced out store (64 threads x float4)
        if (tid < 64) {
            int bb  = tid >> 1;
            int seg = tid & 1;
            float4 v;
            v.x = hst[(seg*4+0)*32 + bb];
            v.y = hst[(seg*4+1)*32 + bb];
            v.z = hst[(seg*4+2)*32 + bb];
            v.w = hst[(seg*4+3)*32 + bb];
            *(float4*)(out + ((size_t)(b0 + bb) * SEQ + t) * (2*HID) + dir*HID + j0 + seg*4) = v;
        }
    }
}

// ---------------- launch ----------------
extern "C" void kernel_launch(void* const* d_in, const int* in_sizes, int n_in,
                              void* d_out, int out_size)
{
    (void)in_sizes; (void)n_in; (void)out_size;
    const int*   words    = (const int*)  d_in[0];
    const int*   lengths  = (const int*)  d_in[1];
    const float* emb      = (const float*)d_in[2];
    const float* l1f_Wih  = (const float*)d_in[3];
    const float* l1f_Whh  = (const float*)d_in[4];
    const float* l1f_bih  = (const float*)d_in[5];
    const float* l1f_bhh  = (const float*)d_in[6];
    const float* l1b_Wih  = (const float*)d_in[7];
    const float* l1b_Whh  = (const float*)d_in[8];
    const float* l1b_bih  = (const float*)d_in[9];
    const float* l1b_bhh  = (const float*)d_in[10];
    const float* l2f_Wih  = (const float*)d_in[11];
    const float* l2f_Whh  = (const float*)d_in[12];
    const float* l2f_bih  = (const float*)d_in[13];
    const float* l2f_bhh  = (const float*)d_in[14];
    const float* l2b_Wih  = (const float*)d_in[15];
    const float* l2b_Whh  = (const float*)d_in[16];
    const float* l2b_bih  = (const float*)d_in[17];
    const float* l2b_bhh  = (const float*)d_in[18];
    const float* cls_W    = (const float*)d_in[19];
    const float* cls_b    = (const float*)d_in[20];
    float* out = (float*)d_out;

    float *px, *pxf, *pxb, *po1, *po2, *ph1, *ph2;
    int *pbar;
    cudaGetSymbolAddress((void**)&px,   g_x);
    cudaGetSymbolAddress((void**)&pxf,  g_xg_f);
    cudaGetSymbolAddress((void**)&pxb,  g_xg_b);
    cudaGetSymbolAddress((void**)&po1,  g_o1);
    cudaGetSymbolAddress((void**)&po2,  g_o2);
    cudaGetSymbolAddress((void**)&ph1,  g_h1);
    cudaGetSymbolAddress((void**)&ph2,  g_h2);
    cudaGetSymbolAddress((void**)&pbar, g_bar);

    cudaFuncSetAttribute(recur_kernel, cudaFuncAttributeMaxDynamicSharedMemorySize, SMEM_RECUR);

    // 1) init
    init_kernel<<<256, 256>>>();

    // 2) embedding
    embed_kernel<<<M_ROWS/8, 256>>>(words, emb);

    // 3) layer-1 input projections
    dim3 gx(G4/128, M_ROWS/128, 2);
    gemm_tf32_dual<<<gx, 256>>>(px, l1f_Wih, l1b_Wih,
                                l1f_bih, l1f_bhh, l1b_bih, l1b_bhh,
                                pxf, pxb, M_ROWS, G4, EMB);

    // 4) layer-1 recurrence
    recur_kernel<<<REC_BLOCKS, 256, SMEM_RECUR>>>(pxf, pxb, l1f_Whh, l1b_Whh,
                                                  lengths, po1, ph1, pbar);

    // 5) layer-2 input projections
    gemm_tf32_dual<<<gx, 256>>>(po1, l2f_Wih, l2b_Wih,
                                l2f_bih, l2f_bhh, l2b_bih, l2b_bhh,
                                pxf, pxb, M_ROWS, G4, 2*HID);

    // 6) layer-2 recurrence
    recur_kernel<<<REC_BLOCKS, 256, SMEM_RECUR>>>(pxf, pxb, l2f_Whh, l2b_Whh,
                                                  lengths, po2, ph2, pbar + SEQ*4*8);

    // 7) classifier (fp32)
    dim3 gc(1, M_ROWS/128, 1);
    sgemm_cls_kernel<<<gc, 256>>>(po2, cls_W, cls_b, out, M_ROWS, NTAGS, 2*HID);
}